// round 1
// baseline (speedup 1.0000x reference)
#include <cuda_runtime.h>
#include <math.h>

// Problem constants
#define Bc   2
#define Tt   512
#define Nf   6
#define Dd   32
#define HIDc 128
#define NHc  4
#define HDc  32
#define Lc   3072      // Tt*Nf
#define GHc  32
#define FDc  128
#define EPSc 1e-5f

// Scratch (device globals: no allocation allowed)
__device__ float d_Q[Bc*NHc*Lc*HDc];     // [b][h][l][d]
__device__ float d_Kg[Bc*NHc*Lc*HDc];
__device__ float d_Vg[Bc*NHc*Lc*HDc];
__device__ float d_TBS[Bc*Tt*HIDc];      // per-time-block V sums, hid layout
__device__ float d_SV[Bc*Tt*HIDc];       // suffix sums of V beyond block t
__device__ float d_attn[Bc*Lc*HIDc];     // attention output (pre o_w)

// ---------------------------------------------------------------------------
__global__ void zero_tbs_kernel() {
    int i = blockIdx.x * blockDim.x + threadIdx.x;
    if (i < Bc*Tt*HIDc) d_TBS[i] = 0.0f;
}

// ---------------------------------------------------------------------------
// Fused gater + gated QKV. One block (128 threads) per token.
__global__ void qkv_gate_kernel(const float* __restrict__ x,
    const float* __restrict__ g_ln_w, const float* __restrict__ g_ln_b,
    const float* __restrict__ g_w1,   const float* __restrict__ g_b1,
    const float* __restrict__ g_w2,   const float* __restrict__ g_b2,
    const float* __restrict__ q_w,    const float* __restrict__ q_b,
    const float* __restrict__ k_w,    const float* __restrict__ k_b,
    const float* __restrict__ v_w,    const float* __restrict__ v_b)
{
    int token = blockIdx.x;            // b*Lc + l
    int b = token / Lc;
    int l = token - b * Lc;
    int tid = threadIdx.x;

    __shared__ float xs[32];
    __shared__ float xns[32];
    __shared__ float gate_s;

    const float* xp = x + (size_t)token * Dd;

    if (tid < 32) {
        float xv = xp[tid];
        xs[tid] = xv;
        float s = xv, s2 = xv * xv;
        #pragma unroll
        for (int o = 16; o; o >>= 1) {
            s  += __shfl_xor_sync(0xffffffffu, s,  o);
            s2 += __shfl_xor_sync(0xffffffffu, s2, o);
        }
        float mu  = s * (1.0f / 32.0f);
        float var = s2 * (1.0f / 32.0f) - mu * mu;
        float inv = rsqrtf(var + EPSc);
        xns[tid] = (xv - mu) * inv * g_ln_w[tid] + g_ln_b[tid];
    }
    __syncthreads();
    if (tid < 32) {
        float h = g_b1[tid];
        #pragma unroll
        for (int dd = 0; dd < 32; ++dd) h += xns[dd] * g_w1[dd * GHc + tid];
        h = h / (1.0f + __expf(-h));           // SiLU
        float gp = h * g_w2[tid];
        #pragma unroll
        for (int o = 16; o; o >>= 1) gp += __shfl_xor_sync(0xffffffffu, gp, o);
        if (tid == 0) gate_s = 1.0f / (1.0f + __expf(-(gp + g_b2[0])));
    }
    __syncthreads();

    float gate = gate_s;
    int c = tid;                                // 0..127
    float q = q_b[c], k = k_b[c], v = v_b[c];
    #pragma unroll
    for (int dd = 0; dd < 32; ++dd) {
        float xd = xs[dd];
        q += xd * q_w[dd * HIDc + c];
        k += xd * k_w[dd * HIDc + c];
        v += xd * v_w[dd * HIDc + c];
    }
    q *= gate; k *= gate; v *= gate;

    int h  = c >> 5;
    int dd2 = c & 31;
    int bh = b * NHc + h;
    size_t idx = ((size_t)bh * Lc + l) * HDc + dd2;
    d_Q[idx] = q; d_Kg[idx] = k; d_Vg[idx] = v;

    atomicAdd(&d_TBS[((size_t)b * Tt + l / Nf) * HIDc + c], v);
}

// ---------------------------------------------------------------------------
// Suffix scan: SV[b][t][c] = sum over time blocks > t of TBS. 1 block, 256 thr.
__global__ void scan_sv_kernel() {
    int tid = threadIdx.x;                 // b*128 + c
    int b = tid >> 7, c = tid & 127;
    float run = 0.0f;
    for (int t = Tt - 1; t >= 0; --t) {
        size_t idx = ((size_t)b * Tt + t) * HIDc + c;
        d_SV[idx] = run;
        run += d_TBS[idx];
    }
}

// ---------------------------------------------------------------------------
// Flash-style block-causal attention with online softmax.
// 256 threads, 8 warps, 4 queries per warp => 32 queries per block.
#define TQ 32
#define TK 32
#define QPW 4
#define KSTR 36   // padded row stride (floats), 16B-aligned, conflict-free
__global__ __launch_bounds__(256) void attn_kernel()
{
    const float SC = 0.17677669529663688f;  // 1/sqrt(32)
    int bx = blockIdx.x;                     // 0..95
    int h  = blockIdx.y;
    int b  = blockIdx.z;
    int l0 = Lc - TQ * (bx + 1);             // longest-work blocks first
    int bh = b * NHc + h;

    const float* Qb = d_Q  + (size_t)bh * Lc * HDc;
    const float* Kb = d_Kg + (size_t)bh * Lc * HDc;
    const float* Vb = d_Vg + (size_t)bh * Lc * HDc;

    __shared__ __align__(16) float qsh[TQ * 32];
    __shared__ __align__(16) float Ksh[TK * KSTR];
    __shared__ __align__(16) float Vsh[TK * KSTR];
    __shared__ __align__(16) float psh[8][TK * 4];

    int tid  = threadIdx.x;
    int w    = tid >> 5;
    int lane = tid & 31;

    // load Q tile (32 rows x 32 contiguous floats)
    *(float4*)(qsh + tid * 4) = *(const float4*)(Qb + (size_t)l0 * 32 + tid * 4);

    int lq0 = l0 + w * QPW;
    int end0 = 6 * ((lq0 + 0) / 6) + 6;
    int end1 = 6 * ((lq0 + 1) / 6) + 6;
    int end2 = 6 * ((lq0 + 2) / 6) + 6;
    int end3 = 6 * ((lq0 + 3) / 6) + 6;
    int end_max = 6 * ((l0 + TQ - 1) / 6) + 6;

    float m0 = -INFINITY, m1 = -INFINITY, m2 = -INFINITY, m3 = -INFINITY;
    float su0 = 0.f, su1 = 0.f, su2 = 0.f, su3 = 0.f;
    float a0 = 0.f, a1 = 0.f, a2 = 0.f, a3 = 0.f;

    int jrow = tid >> 3;
    int jcol = (tid & 7) * 4;

    for (int kb = 0; kb < end_max; kb += TK) {
        __syncthreads();
        {   // cooperative tile load: 256 threads x float4 each for K and V
            float4 kv = *(const float4*)(Kb + (size_t)(kb + jrow) * 32 + jcol);
            float4 vv = *(const float4*)(Vb + (size_t)(kb + jrow) * 32 + jcol);
            float* kp = Ksh + jrow * KSTR + jcol;
            kp[0] = kv.x; kp[1] = kv.y; kp[2] = kv.z; kp[3] = kv.w;
            float* vp = Vsh + jrow * KSTR + jcol;
            vp[0] = vv.x; vp[1] = vv.y; vp[2] = vv.z; vp[3] = vv.w;
        }
        __syncthreads();

        // ---- scoring: lane = key ----
        float s0 = 0.f, s1 = 0.f, s2 = 0.f, s3 = 0.f;
        const float4* kr = (const float4*)(Ksh + lane * KSTR);
        const float4* q0 = (const float4*)(qsh + (w * QPW + 0) * 32);
        const float4* q1 = (const float4*)(qsh + (w * QPW + 1) * 32);
        const float4* q2 = (const float4*)(qsh + (w * QPW + 2) * 32);
        const float4* q3 = (const float4*)(qsh + (w * QPW + 3) * 32);
        #pragma unroll
        for (int dv = 0; dv < 8; ++dv) {
            float4 kv = kr[dv];
            float4 qa = q0[dv]; s0 += kv.x*qa.x + kv.y*qa.y + kv.z*qa.z + kv.w*qa.w;
            float4 qb2 = q1[dv]; s1 += kv.x*qb2.x + kv.y*qb2.y + kv.z*qb2.z + kv.w*qb2.w;
            float4 qc = q2[dv]; s2 += kv.x*qc.x + kv.y*qc.y + kv.z*qc.z + kv.w*qc.w;
            float4 qd = q3[dv]; s3 += kv.x*qd.x + kv.y*qd.y + kv.z*qd.z + kv.w*qd.w;
        }
        int j = kb + lane;
        s0 = (j < end0) ? s0 * SC : -INFINITY;
        s1 = (j < end1) ? s1 * SC : -INFINITY;
        s2 = (j < end2) ? s2 * SC : -INFINITY;
        s3 = (j < end3) ? s3 * SC : -INFINITY;

        float t0 = s0, t1 = s1, t2 = s2, t3 = s3;
        #pragma unroll
        for (int o = 16; o; o >>= 1) {
            t0 = fmaxf(t0, __shfl_xor_sync(0xffffffffu, t0, o));
            t1 = fmaxf(t1, __shfl_xor_sync(0xffffffffu, t1, o));
            t2 = fmaxf(t2, __shfl_xor_sync(0xffffffffu, t2, o));
            t3 = fmaxf(t3, __shfl_xor_sync(0xffffffffu, t3, o));
        }
        float nm0 = fmaxf(m0, t0), nm1 = fmaxf(m1, t1);
        float nm2 = fmaxf(m2, t2), nm3 = fmaxf(m3, t3);
        float sc0 = (m0 == -INFINITY) ? 0.f : __expf(m0 - nm0);
        float sc1 = (m1 == -INFINITY) ? 0.f : __expf(m1 - nm1);
        float sc2 = (m2 == -INFINITY) ? 0.f : __expf(m2 - nm2);
        float sc3 = (m3 == -INFINITY) ? 0.f : __expf(m3 - nm3);
        float p0 = (s0 == -INFINITY) ? 0.f : __expf(s0 - nm0);
        float p1 = (s1 == -INFINITY) ? 0.f : __expf(s1 - nm1);
        float p2 = (s2 == -INFINITY) ? 0.f : __expf(s2 - nm2);
        float p3 = (s3 == -INFINITY) ? 0.f : __expf(s3 - nm3);

        float u0 = p0, u1 = p1, u2 = p2, u3 = p3;
        #pragma unroll
        for (int o = 16; o; o >>= 1) {
            u0 += __shfl_xor_sync(0xffffffffu, u0, o);
            u1 += __shfl_xor_sync(0xffffffffu, u1, o);
            u2 += __shfl_xor_sync(0xffffffffu, u2, o);
            u3 += __shfl_xor_sync(0xffffffffu, u3, o);
        }
        su0 = su0 * sc0 + u0;  su1 = su1 * sc1 + u1;
        su2 = su2 * sc2 + u2;  su3 = su3 * sc3 + u3;
        a0 *= sc0; a1 *= sc1; a2 *= sc2; a3 *= sc3;
        m0 = nm0; m1 = nm1; m2 = nm2; m3 = nm3;

        float4 pv = make_float4(p0, p1, p2, p3);
        *(float4*)(&psh[w][lane * 4]) = pv;
        __syncwarp();

        // ---- accumulate: lane = dim ----
        const float4* pp = (const float4*)(&psh[w][0]);
        #pragma unroll
        for (int jj = 0; jj < TK; ++jj) {
            float v = Vsh[jj * KSTR + lane];
            float4 pj = pp[jj];
            a0 += pj.x * v; a1 += pj.y * v; a2 += pj.z * v; a3 += pj.w * v;
        }
        __syncwarp();
    }

    float i0 = 1.0f / su0, i1 = 1.0f / su1, i2 = 1.0f / su2, i3 = 1.0f / su3;
    size_t obase = ((size_t)b * Lc + lq0) * HIDc + h * HDc + lane;
    d_attn[obase + 0 * HIDc] = a0 * i0;
    d_attn[obase + 1 * HIDc] = a1 * i1;
    d_attn[obase + 2 * HIDc] = a2 * i2;
    d_attn[obase + 3 * HIDc] = a3 * i3;
}

// ---------------------------------------------------------------------------
// Pool(6) [+ exact 1e-9 masked-tail term] -> o_w -> LN -> f_w -> SiLU.
__global__ void final_kernel(
    const float* __restrict__ o_w,    const float* __restrict__ o_b,
    const float* __restrict__ f_ln_w, const float* __restrict__ f_ln_b,
    const float* __restrict__ f_w,    const float* __restrict__ f_b,
    float* __restrict__ out)
{
    int bt = blockIdx.x;
    int b = bt / Tt, t = bt - b * Tt;
    int c = threadIdx.x;                    // 0..127
    int w = c >> 5, lane = c & 31;

    __shared__ float sp[128], sln[128];
    __shared__ float redA[4], redB[4];

    float p = 0.0f;
    #pragma unroll
    for (int k = 0; k < Nf; ++k)
        p += d_attn[((size_t)b * Lc + t * Nf + k) * HIDc + c];
    p = p * (1.0f / Nf) + 1e-9f * d_SV[((size_t)b * Tt + t) * HIDc + c];
    sp[c] = p;
    __syncthreads();

    float o = o_b[c];
    #pragma unroll 8
    for (int dd = 0; dd < 128; ++dd) o += sp[dd] * o_w[dd * HIDc + c];

    float s = o, s2 = o * o;
    #pragma unroll
    for (int off = 16; off; off >>= 1) {
        s  += __shfl_xor_sync(0xffffffffu, s,  off);
        s2 += __shfl_xor_sync(0xffffffffu, s2, off);
    }
    if (lane == 0) { redA[w] = s; redB[w] = s2; }
    __syncthreads();
    float S  = redA[0] + redA[1] + redA[2] + redA[3];
    float S2 = redB[0] + redB[1] + redB[2] + redB[3];
    float mu  = S * (1.0f / 128.0f);
    float var = S2 * (1.0f / 128.0f) - mu * mu;
    float ln = (o - mu) * rsqrtf(var + EPSc) * f_ln_w[c] + f_ln_b[c];
    sln[c] = ln;
    __syncthreads();

    float f = f_b[c];
    #pragma unroll 8
    for (int dd = 0; dd < 128; ++dd) f += sln[dd] * f_w[dd * HIDc + c];
    out[((size_t)b * Tt + t) * FDc + c] = f / (1.0f + __expf(-f));
}

// ---------------------------------------------------------------------------
extern "C" void kernel_launch(void* const* d_in, const int* in_sizes, int n_in,
                              void* d_out, int out_size)
{
    const float* x      = (const float*)d_in[0];
    const float* g_ln_w = (const float*)d_in[1];
    const float* g_ln_b = (const float*)d_in[2];
    const float* g_w1   = (const float*)d_in[3];
    const float* g_b1   = (const float*)d_in[4];
    const float* g_w2   = (const float*)d_in[5];
    const float* g_b2   = (const float*)d_in[6];
    const float* q_w    = (const float*)d_in[7];
    const float* q_b    = (const float*)d_in[8];
    const float* k_w    = (const float*)d_in[9];
    const float* k_b    = (const float*)d_in[10];
    const float* v_w    = (const float*)d_in[11];
    const float* v_b    = (const float*)d_in[12];
    const float* o_w    = (const float*)d_in[13];
    const float* o_b    = (const float*)d_in[14];
    const float* f_ln_w = (const float*)d_in[15];
    const float* f_ln_b = (const float*)d_in[16];
    const float* f_w    = (const float*)d_in[17];
    const float* f_b    = (const float*)d_in[18];

    zero_tbs_kernel<<<(Bc*Tt*HIDc + 255) / 256, 256>>>();
    qkv_gate_kernel<<<Bc * Lc, 128>>>(x, g_ln_w, g_ln_b, g_w1, g_b1, g_w2, g_b2,
                                      q_w, q_b, k_w, k_b, v_w, v_b);
    scan_sv_kernel<<<1, 256>>>();
    attn_kernel<<<dim3(Lc / TQ, NHc, Bc), 256>>>();
    final_kernel<<<Bc * Tt, 128>>>(o_w, o_b, f_ln_w, f_ln_b, f_w, f_b,
                                   (float*)d_out);
}

// round 2
// speedup vs baseline: 1.5644x; 1.5644x over previous
#include <cuda_runtime.h>
#include <math.h>

// Problem constants
#define Bc   2
#define Tt   512
#define Nf   6
#define Dd   32
#define HIDc 128
#define NHc  4
#define HDc  32
#define Lc   3072      // Tt*Nf
#define GHc  32
#define FDc  128
#define EPSc 1e-5f

// Scratch (device globals: no allocation allowed)
__device__ float d_Q[Bc*NHc*Lc*HDc];     // [b][h][l][d]  (Q pre-scaled by 1/sqrt(HD))
__device__ float d_Kg[Bc*NHc*Lc*HDc];
__device__ float d_Vg[Bc*NHc*Lc*HDc];
__device__ float d_TBS[Bc*Tt*HIDc];      // per-time-block V sums, hid layout
__device__ float d_SV[Bc*Tt*HIDc];       // suffix sums of V beyond block t
__device__ float d_attn[Bc*Lc*HIDc];     // attention output (pre o_w)

// ---- packed fp32x2 helpers (sm_103a FFMA2 path) ----
__device__ __forceinline__ void fma2(unsigned long long &d,
                                     unsigned long long a,
                                     unsigned long long b) {
    asm("fma.rn.f32x2 %0, %1, %2, %0;" : "+l"(d) : "l"(a), "l"(b));
}
__device__ __forceinline__ unsigned long long pack2(float x, float y) {
    unsigned long long r;
    asm("mov.b64 %0, {%1, %2};" : "=l"(r) : "f"(x), "f"(y));
    return r;
}
__device__ __forceinline__ float2 unpack2(unsigned long long v) {
    float2 r;
    asm("mov.b64 {%0, %1}, %2;" : "=f"(r.x), "=f"(r.y) : "l"(v));
    return r;
}

// ---------------------------------------------------------------------------
__global__ void zero_tbs_kernel() {
    int i = blockIdx.x * blockDim.x + threadIdx.x;
    if (i < Bc*Tt*HIDc) d_TBS[i] = 0.0f;
}

// ---------------------------------------------------------------------------
// Fused gater + gated QKV. One block (128 threads) per 8 tokens.
#define QTOK 8
__global__ __launch_bounds__(128) void qkv_gate_kernel(const float* __restrict__ x,
    const float* __restrict__ g_ln_w, const float* __restrict__ g_ln_b,
    const float* __restrict__ g_w1,   const float* __restrict__ g_b1,
    const float* __restrict__ g_w2,   const float* __restrict__ g_b2,
    const float* __restrict__ q_w,    const float* __restrict__ q_b,
    const float* __restrict__ k_w,    const float* __restrict__ k_b,
    const float* __restrict__ v_w,    const float* __restrict__ v_b)
{
    const float SC = 0.17677669529663688f;  // 1/sqrt(32)
    int t0 = blockIdx.x * QTOK;             // global token base (b*Lc + l)
    int tid = threadIdx.x;
    int w = tid >> 5, lane = tid & 31;

    __shared__ float xs[QTOK][32];
    __shared__ float gate[QTOK];

    // load x for 8 tokens
    #pragma unroll
    for (int i = tid; i < QTOK*32; i += 128)
        xs[i >> 5][i & 31] = x[(size_t)t0 * 32 + i];
    __syncthreads();

    // gater: warp w handles tokens 2w, 2w+1 (lanes = dims)
    #pragma unroll
    for (int kk = 0; kk < 2; ++kk) {
        int t = w * 2 + kk;
        float xv = xs[t][lane];
        float s = xv, s2 = xv * xv;
        #pragma unroll
        for (int o = 16; o; o >>= 1) {
            s  += __shfl_xor_sync(0xffffffffu, s,  o);
            s2 += __shfl_xor_sync(0xffffffffu, s2, o);
        }
        float mu  = s * (1.0f / 32.0f);
        float var = s2 * (1.0f / 32.0f) - mu * mu;
        float xn = (xv - mu) * rsqrtf(var + EPSc) * g_ln_w[lane] + g_ln_b[lane];
        float h = g_b1[lane];
        #pragma unroll
        for (int d = 0; d < 32; ++d)
            h += __shfl_sync(0xffffffffu, xn, d) * g_w1[d * GHc + lane];
        h = h / (1.0f + __expf(-h));
        float gp = h * g_w2[lane];
        #pragma unroll
        for (int o = 16; o; o >>= 1) gp += __shfl_xor_sync(0xffffffffu, gp, o);
        if (lane == 0) gate[t] = 1.0f / (1.0f + __expf(-(gp + g_b2[0])));
    }
    __syncthreads();

    // gated QKV: thread c = output channel, weight loaded once, applied to 8 tokens
    int c = tid;
    float q[QTOK], k[QTOK], v[QTOK];
    float qb = q_b[c], kb = k_b[c], vb = v_b[c];
    #pragma unroll
    for (int t = 0; t < QTOK; ++t) { q[t] = qb; k[t] = kb; v[t] = vb; }
    #pragma unroll
    for (int dd = 0; dd < 32; ++dd) {
        float wq = q_w[dd * HIDc + c];
        float wk = k_w[dd * HIDc + c];
        float wv = v_w[dd * HIDc + c];
        #pragma unroll
        for (int t = 0; t < QTOK; ++t) {
            float xd = xs[t][dd];
            q[t] += xd * wq; k[t] += xd * wk; v[t] += xd * wv;
        }
    }

    int hh = c >> 5, d2 = c & 31;
    #pragma unroll
    for (int t = 0; t < QTOK; ++t) {
        int token = t0 + t;
        int b = token / Lc, l = token - b * Lc;
        float g = gate[t];
        size_t idx = ((size_t)(b * NHc + hh) * Lc + l) * HDc + d2;
        d_Q[idx]  = q[t] * g * SC;
        d_Kg[idx] = k[t] * g;
        float vg = v[t] * g;
        d_Vg[idx] = vg;
        atomicAdd(&d_TBS[((size_t)b * Tt + l / Nf) * HIDc + c], vg);
    }
}

// ---------------------------------------------------------------------------
// Parallel suffix scan: SV[b][t][c] = sum over time blocks > t of TBS.
// grid = Bc*HIDc blocks, block = 512 threads (Hillis-Steele).
__global__ void scan_sv_kernel() {
    int col = blockIdx.x;
    int b = col >> 7, c = col & 127;
    int t = threadIdx.x;
    __shared__ float sh[Tt];
    size_t idx = ((size_t)b * Tt + t) * HIDc + c;
    float val = d_TBS[idx];
    sh[t] = val;
    __syncthreads();
    #pragma unroll
    for (int off = 1; off < Tt; off <<= 1) {
        float add = (t + off < Tt) ? sh[t + off] : 0.0f;
        __syncthreads();
        sh[t] += add;
        __syncthreads();
    }
    d_SV[idx] = sh[t] - val;   // exclusive suffix sum
}

// ---------------------------------------------------------------------------
// Block-causal attention, no online-max (scores bounded), packed FFMA2.
// 256 threads, 8 warps, 4 queries per warp => 32 queries per block.
#define TQ 32
#define TK 32
#define QPW 4
#define KSTR 36   // padded row stride (floats), 16B-aligned, conflict-free
__global__ __launch_bounds__(256) void attn_kernel()
{
    int bx = blockIdx.x;                     // 0..95
    int h  = blockIdx.y;
    int b  = blockIdx.z;
    int l0 = Lc - TQ * (bx + 1);             // longest-work blocks first
    int bh = b * NHc + h;

    const float* Qb = d_Q  + (size_t)bh * Lc * HDc;
    const float* Kb = d_Kg + (size_t)bh * Lc * HDc;
    const float* Vb = d_Vg + (size_t)bh * Lc * HDc;

    __shared__ __align__(16) float qsh[TQ * 32];
    __shared__ __align__(16) float Ksh[TK * KSTR];
    __shared__ __align__(16) float Vsh[TK * KSTR];
    __shared__ __align__(16) float psh[8][TK * 4];

    int tid  = threadIdx.x;
    int w    = tid >> 5;
    int lane = tid & 31;

    // load Q tile (already pre-scaled by 1/sqrt(HD))
    *(float4*)(qsh + tid * 4) = *(const float4*)(Qb + (size_t)l0 * 32 + tid * 4);

    int lq0 = l0 + w * QPW;
    int end0 = 6 * ((lq0 + 0) / 6) + 6;
    int end1 = 6 * ((lq0 + 1) / 6) + 6;
    int end2 = 6 * ((lq0 + 2) / 6) + 6;
    int end3 = 6 * ((lq0 + 3) / 6) + 6;
    int end_max = 6 * ((l0 + TQ - 1) / 6) + 6;

    float su0 = 0.f, su1 = 0.f, su2 = 0.f, su3 = 0.f;
    unsigned long long a01 = 0ull, a23 = 0ull;   // packed accumulators (q0,q1),(q2,q3)

    int jrow = tid >> 3;
    int jcol = (tid & 7) * 4;

    // prefetch first tile
    float4 kf4 = *(const float4*)(Kb + (size_t)jrow * 32 + jcol);
    float4 vf4 = *(const float4*)(Vb + (size_t)jrow * 32 + jcol);

    for (int kb = 0; kb < end_max; kb += TK) {
        __syncthreads();
        {
            float* kp = Ksh + jrow * KSTR + jcol;
            kp[0] = kf4.x; kp[1] = kf4.y; kp[2] = kf4.z; kp[3] = kf4.w;
            float* vp = Vsh + jrow * KSTR + jcol;
            vp[0] = vf4.x; vp[1] = vf4.y; vp[2] = vf4.z; vp[3] = vf4.w;
        }
        if (kb + TK < end_max) {   // prefetch next tile, overlaps compute
            kf4 = *(const float4*)(Kb + (size_t)(kb + TK + jrow) * 32 + jcol);
            vf4 = *(const float4*)(Vb + (size_t)(kb + TK + jrow) * 32 + jcol);
        }
        __syncthreads();

        // ---- scoring: lane = key, dims packed in pairs (FFMA2) ----
        unsigned long long s0 = 0ull, s1 = 0ull, s2 = 0ull, s3 = 0ull;
        const ulonglong2* kr = (const ulonglong2*)(Ksh + lane * KSTR);
        const ulonglong2* q0 = (const ulonglong2*)(qsh + (w * QPW + 0) * 32);
        const ulonglong2* q1 = (const ulonglong2*)(qsh + (w * QPW + 1) * 32);
        const ulonglong2* q2 = (const ulonglong2*)(qsh + (w * QPW + 2) * 32);
        const ulonglong2* q3 = (const ulonglong2*)(qsh + (w * QPW + 3) * 32);
        #pragma unroll
        for (int dv = 0; dv < 8; ++dv) {
            ulonglong2 kk = kr[dv];
            ulonglong2 qa = q0[dv]; fma2(s0, kk.x, qa.x); fma2(s0, kk.y, qa.y);
            ulonglong2 qb2 = q1[dv]; fma2(s1, kk.x, qb2.x); fma2(s1, kk.y, qb2.y);
            ulonglong2 qc = q2[dv]; fma2(s2, kk.x, qc.x); fma2(s2, kk.y, qc.y);
            ulonglong2 qd = q3[dv]; fma2(s3, kk.x, qd.x); fma2(s3, kk.y, qd.y);
        }
        float2 f0 = unpack2(s0), f1 = unpack2(s1), f2 = unpack2(s2), f3 = unpack2(s3);
        int j = kb + lane;
        float p0 = (j < end0) ? __expf(f0.x + f0.y) : 0.0f;
        float p1 = (j < end1) ? __expf(f1.x + f1.y) : 0.0f;
        float p2 = (j < end2) ? __expf(f2.x + f2.y) : 0.0f;
        float p3 = (j < end3) ? __expf(f3.x + f3.y) : 0.0f;
        su0 += p0; su1 += p1; su2 += p2; su3 += p3;

        *(float4*)(&psh[w][lane * 4]) = make_float4(p0, p1, p2, p3);
        __syncwarp();

        // ---- accumulate: lane = dim, queries packed in pairs (FFMA2) ----
        const ulonglong2* pp = (const ulonglong2*)(&psh[w][0]);
        #pragma unroll
        for (int jj = 0; jj < TK; ++jj) {
            float v = Vsh[jj * KSTR + lane];
            unsigned long long vv = pack2(v, v);
            ulonglong2 pj = pp[jj];
            fma2(a01, vv, pj.x);
            fma2(a23, vv, pj.y);
        }
        __syncwarp();
    }

    // final reduction of denominators across lanes (keys)
    #pragma unroll
    for (int o = 16; o; o >>= 1) {
        su0 += __shfl_xor_sync(0xffffffffu, su0, o);
        su1 += __shfl_xor_sync(0xffffffffu, su1, o);
        su2 += __shfl_xor_sync(0xffffffffu, su2, o);
        su3 += __shfl_xor_sync(0xffffffffu, su3, o);
    }

    float2 aq01 = unpack2(a01), aq23 = unpack2(a23);
    size_t obase = ((size_t)b * Lc + lq0) * HIDc + h * HDc + lane;
    d_attn[obase + 0 * HIDc] = aq01.x / su0;
    d_attn[obase + 1 * HIDc] = aq01.y / su1;
    d_attn[obase + 2 * HIDc] = aq23.x / su2;
    d_attn[obase + 3 * HIDc] = aq23.y / su3;
}

// ---------------------------------------------------------------------------
// Pool(6) [+ exact 1e-9 masked-tail term] -> o_w -> LN -> f_w -> SiLU.
// 8 (b,t) rows per block; weights loaded once and applied to all 8 rows.
#define FTOK 8
__global__ __launch_bounds__(128) void final_kernel(
    const float* __restrict__ o_w,    const float* __restrict__ o_b,
    const float* __restrict__ f_ln_w, const float* __restrict__ f_ln_b,
    const float* __restrict__ f_w,    const float* __restrict__ f_b,
    float* __restrict__ out)
{
    int p0 = blockIdx.x * FTOK;
    int c = threadIdx.x;
    int w = c >> 5, lane = c & 31;

    __shared__ float sp[FTOK][128];
    __shared__ float sln[FTOK][128];
    __shared__ float redA[FTOK][4], redB[FTOK][4];

    #pragma unroll
    for (int t = 0; t < FTOK; ++t) {
        int bt = p0 + t;
        int b = bt / Tt, tt = bt - b * Tt;
        float p = 0.0f;
        #pragma unroll
        for (int k = 0; k < Nf; ++k)
            p += d_attn[((size_t)b * Lc + tt * Nf + k) * HIDc + c];
        sp[t][c] = p * (1.0f / Nf) + 1e-9f * d_SV[((size_t)b * Tt + tt) * HIDc + c];
    }
    __syncthreads();

    float acc[FTOK];
    float ob = o_b[c];
    #pragma unroll
    for (int t = 0; t < FTOK; ++t) acc[t] = ob;
    #pragma unroll 4
    for (int dd = 0; dd < 128; ++dd) {
        float wv = o_w[dd * HIDc + c];
        #pragma unroll
        for (int t = 0; t < FTOK; ++t) acc[t] += sp[t][dd] * wv;
    }

    #pragma unroll
    for (int t = 0; t < FTOK; ++t) {
        float s = acc[t], s2 = acc[t] * acc[t];
        #pragma unroll
        for (int o = 16; o; o >>= 1) {
            s  += __shfl_xor_sync(0xffffffffu, s,  o);
            s2 += __shfl_xor_sync(0xffffffffu, s2, o);
        }
        if (lane == 0) { redA[t][w] = s; redB[t][w] = s2; }
    }
    __syncthreads();
    #pragma unroll
    for (int t = 0; t < FTOK; ++t) {
        float S  = redA[t][0] + redA[t][1] + redA[t][2] + redA[t][3];
        float S2 = redB[t][0] + redB[t][1] + redB[t][2] + redB[t][3];
        float mu  = S * (1.0f / 128.0f);
        float var = S2 * (1.0f / 128.0f) - mu * mu;
        sln[t][c] = (acc[t] - mu) * rsqrtf(var + EPSc) * f_ln_w[c] + f_ln_b[c];
    }
    __syncthreads();

    float f[FTOK];
    float fb = f_b[c];
    #pragma unroll
    for (int t = 0; t < FTOK; ++t) f[t] = fb;
    #pragma unroll 4
    for (int dd = 0; dd < 128; ++dd) {
        float wv = f_w[dd * HIDc + c];
        #pragma unroll
        for (int t = 0; t < FTOK; ++t) f[t] += sln[t][dd] * wv;
    }
    #pragma unroll
    for (int t = 0; t < FTOK; ++t) {
        float ff = f[t];
        out[(size_t)(p0 + t) * FDc + c] = ff / (1.0f + __expf(-ff));
    }
}

// ---------------------------------------------------------------------------
extern "C" void kernel_launch(void* const* d_in, const int* in_sizes, int n_in,
                              void* d_out, int out_size)
{
    const float* x      = (const float*)d_in[0];
    const float* g_ln_w = (const float*)d_in[1];
    const float* g_ln_b = (const float*)d_in[2];
    const float* g_w1   = (const float*)d_in[3];
    const float* g_b1   = (const float*)d_in[4];
    const float* g_w2   = (const float*)d_in[5];
    const float* g_b2   = (const float*)d_in[6];
    const float* q_w    = (const float*)d_in[7];
    const float* q_b    = (const float*)d_in[8];
    const float* k_w    = (const float*)d_in[9];
    const float* k_b    = (const float*)d_in[10];
    const float* v_w    = (const float*)d_in[11];
    const float* v_b    = (const float*)d_in[12];
    const float* o_w    = (const float*)d_in[13];
    const float* o_b    = (const float*)d_in[14];
    const float* f_ln_w = (const float*)d_in[15];
    const float* f_ln_b = (const float*)d_in[16];
    const float* f_w    = (const float*)d_in[17];
    const float* f_b    = (const float*)d_in[18];

    zero_tbs_kernel<<<(Bc*Tt*HIDc + 255) / 256, 256>>>();
    qkv_gate_kernel<<<(Bc * Lc) / QTOK, 128>>>(x, g_ln_w, g_ln_b, g_w1, g_b1,
                                               g_w2, g_b2, q_w, q_b, k_w, k_b,
                                               v_w, v_b);
    scan_sv_kernel<<<Bc * HIDc, Tt>>>();
    attn_kernel<<<dim3(Lc / TQ, NHc, Bc), 256>>>();
    final_kernel<<<(Bc * Tt) / FTOK, 128>>>(o_w, o_b, f_ln_w, f_ln_b, f_w, f_b,
                                            (float*)d_out);
}

// round 3
// speedup vs baseline: 2.6706x; 1.7071x over previous
#include <cuda_runtime.h>
#include <math.h>

// Problem constants
#define Bc   2
#define Tt   512
#define Nf   6
#define Dd   32
#define HIDc 128
#define NHc  4
#define HDc  32
#define Lc   3072      // Tt*Nf
#define GHc  32
#define FDc  128
#define EPSc 1e-5f

// Scratch (device globals: no allocation allowed)
__device__ float d_Q[Bc*NHc*Lc*HDc];     // [b][h][l][d]  (Q pre-scaled, tf32-rounded)
__device__ float d_Kg[Bc*NHc*Lc*HDc];
__device__ float d_Vg[Bc*NHc*Lc*HDc];
__device__ float d_TBS[Bc*Tt*HIDc];      // per-time-block V sums, hid layout
__device__ float d_SV[Bc*Tt*HIDc];       // suffix sums of V beyond block t
__device__ float d_attn[Bc*Lc*HIDc];     // attention output (pre o_w)

__device__ __forceinline__ float to_tf32(float x) {
    float r;
    asm("cvt.rna.tf32.f32 %0, %1;" : "=f"(r) : "f"(x));
    return r;
}

// D(16x8) += A(16x8,tf32) * B(8x8,tf32), fp32 accum.
__device__ __forceinline__ void mma_tf32(float c[4],
    unsigned a0, unsigned a1, unsigned a2, unsigned a3,
    unsigned b0, unsigned b1)
{
    asm volatile(
        "mma.sync.aligned.m16n8k8.row.col.f32.tf32.tf32.f32 "
        "{%0,%1,%2,%3}, {%4,%5,%6,%7}, {%8,%9}, {%0,%1,%2,%3};"
        : "+f"(c[0]), "+f"(c[1]), "+f"(c[2]), "+f"(c[3])
        : "r"(a0), "r"(a1), "r"(a2), "r"(a3), "r"(b0), "r"(b1));
}

// ---------------------------------------------------------------------------
__global__ void zero_tbs_kernel() {
    int i = blockIdx.x * blockDim.x + threadIdx.x;
    if (i < Bc*Tt*HIDc) d_TBS[i] = 0.0f;
}

// ---------------------------------------------------------------------------
// Fused gater + gated QKV. One block (128 threads) per 8 tokens.
#define QTOK 8
__global__ __launch_bounds__(128) void qkv_gate_kernel(const float* __restrict__ x,
    const float* __restrict__ g_ln_w, const float* __restrict__ g_ln_b,
    const float* __restrict__ g_w1,   const float* __restrict__ g_b1,
    const float* __restrict__ g_w2,   const float* __restrict__ g_b2,
    const float* __restrict__ q_w,    const float* __restrict__ q_b,
    const float* __restrict__ k_w,    const float* __restrict__ k_b,
    const float* __restrict__ v_w,    const float* __restrict__ v_b)
{
    const float SC = 0.17677669529663688f;  // 1/sqrt(32)
    int t0 = blockIdx.x * QTOK;
    int tid = threadIdx.x;
    int w = tid >> 5, lane = tid & 31;

    __shared__ float xs[QTOK][32];
    __shared__ float gate[QTOK];

    #pragma unroll
    for (int i = tid; i < QTOK*32; i += 128)
        xs[i >> 5][i & 31] = x[(size_t)t0 * 32 + i];
    __syncthreads();

    #pragma unroll
    for (int kk = 0; kk < 2; ++kk) {
        int t = w * 2 + kk;
        float xv = xs[t][lane];
        float s = xv, s2 = xv * xv;
        #pragma unroll
        for (int o = 16; o; o >>= 1) {
            s  += __shfl_xor_sync(0xffffffffu, s,  o);
            s2 += __shfl_xor_sync(0xffffffffu, s2, o);
        }
        float mu  = s * (1.0f / 32.0f);
        float var = s2 * (1.0f / 32.0f) - mu * mu;
        float xn = (xv - mu) * rsqrtf(var + EPSc) * g_ln_w[lane] + g_ln_b[lane];
        float h = g_b1[lane];
        #pragma unroll
        for (int d = 0; d < 32; ++d)
            h += __shfl_sync(0xffffffffu, xn, d) * g_w1[d * GHc + lane];
        h = h / (1.0f + __expf(-h));
        float gp = h * g_w2[lane];
        #pragma unroll
        for (int o = 16; o; o >>= 1) gp += __shfl_xor_sync(0xffffffffu, gp, o);
        if (lane == 0) gate[t] = 1.0f / (1.0f + __expf(-(gp + g_b2[0])));
    }
    __syncthreads();

    int c = tid;
    float q[QTOK], k[QTOK], v[QTOK];
    float qb = q_b[c], kb = k_b[c], vb = v_b[c];
    #pragma unroll
    for (int t = 0; t < QTOK; ++t) { q[t] = qb; k[t] = kb; v[t] = vb; }
    #pragma unroll
    for (int dd = 0; dd < 32; ++dd) {
        float wq = q_w[dd * HIDc + c];
        float wk = k_w[dd * HIDc + c];
        float wv = v_w[dd * HIDc + c];
        #pragma unroll
        for (int t = 0; t < QTOK; ++t) {
            float xd = xs[t][dd];
            q[t] += xd * wq; k[t] += xd * wk; v[t] += xd * wv;
        }
    }

    int hh = c >> 5, d2 = c & 31;
    #pragma unroll
    for (int t = 0; t < QTOK; ++t) {
        int token = t0 + t;
        int b = token / Lc, l = token - b * Lc;
        float g = gate[t];
        size_t idx = ((size_t)(b * NHc + hh) * Lc + l) * HDc + d2;
        d_Q[idx]  = to_tf32(q[t] * g * SC);
        d_Kg[idx] = to_tf32(k[t] * g);
        float vg = to_tf32(v[t] * g);
        d_Vg[idx] = vg;
        atomicAdd(&d_TBS[((size_t)b * Tt + l / Nf) * HIDc + c], vg);
    }
}

// ---------------------------------------------------------------------------
// Parallel suffix scan: SV[b][t][c] = sum over time blocks > t of TBS.
__global__ void scan_sv_kernel() {
    int col = blockIdx.x;
    int b = col >> 7, c = col & 127;
    int t = threadIdx.x;
    __shared__ float sh[Tt];
    size_t idx = ((size_t)b * Tt + t) * HIDc + c;
    float val = d_TBS[idx];
    sh[t] = val;
    __syncthreads();
    #pragma unroll
    for (int off = 1; off < Tt; off <<= 1) {
        float add = (t + off < Tt) ? sh[t + off] : 0.0f;
        __syncthreads();
        sh[t] += add;
        __syncthreads();
    }
    d_SV[idx] = sh[t] - val;   // exclusive suffix sum
}

// ---------------------------------------------------------------------------
// Tensor-core (tf32 mma.sync) block-causal attention, no online-max.
// 128 threads, 4 warps x 16 queries = 64 queries/CTA, 32-key tiles.
#define TQ3 64
#define TK3 32
#define KST 36   // K/V smem row stride (floats)
#define PST 68   // psh row stride (floats)
__global__ __launch_bounds__(128) void attn_kernel()
{
    int bx = blockIdx.x;                     // 0..47
    int h  = blockIdx.y;
    int b  = blockIdx.z;
    int l0 = Lc - TQ3 * (bx + 1);            // longest-work blocks first
    int bh = b * NHc + h;

    const float* Qb = d_Q  + (size_t)bh * Lc * HDc;
    const float* Kb = d_Kg + (size_t)bh * Lc * HDc;
    const float* Vb = d_Vg + (size_t)bh * Lc * HDc;

    __shared__ __align__(16) float Ksh[TK3 * KST];
    __shared__ __align__(16) float Vsh[TK3 * KST];
    __shared__ __align__(16) float psh[TK3 * PST];  // P^T: [key][64 queries]

    int tid  = threadIdx.x;
    int w    = tid >> 5;
    int lane = tid & 31;
    int g    = lane >> 2;        // groupID
    int tig  = lane & 3;         // thread-in-group
    int qbase = w * 16;

    // Q A-fragments (per k-step s: dims 8s..8s+7), held in registers
    unsigned qa[4][4];
    const float* Qp = Qb + (size_t)(l0 + qbase) * 32;
    #pragma unroll
    for (int s = 0; s < 4; ++s) {
        qa[s][0] = __float_as_uint(Qp[(size_t)g * 32 + 8*s + tig]);
        qa[s][1] = __float_as_uint(Qp[(size_t)(g + 8) * 32 + 8*s + tig]);
        qa[s][2] = __float_as_uint(Qp[(size_t)g * 32 + 8*s + tig + 4]);
        qa[s][3] = __float_as_uint(Qp[(size_t)(g + 8) * 32 + 8*s + tig + 4]);
    }

    int endA = 6 * ((l0 + qbase + g) / 6) + 6;        // causal end, row g
    int endB = 6 * ((l0 + qbase + g + 8) / 6) + 6;    // causal end, row g+8
    int wend = 6 * ((l0 + qbase + 15) / 6) + 6;       // warp's max end
    int emax = 6 * ((l0 + TQ3 - 1) / 6) + 6;          // CTA's max end

    float o[2][2][4] = {};       // O^T accum [md][nq][reg]
    float su_lo = 0.f, su_hi = 0.f;

    // tile loader mapping: 128 thr -> 32 rows x (8 floats each)
    int trow = tid >> 2;
    int tcol = (tid & 3) * 8;

    float4 kA = *(const float4*)(Kb + (size_t)trow * 32 + tcol);
    float4 kB = *(const float4*)(Kb + (size_t)trow * 32 + tcol + 4);
    float4 vA = *(const float4*)(Vb + (size_t)trow * 32 + tcol);
    float4 vB = *(const float4*)(Vb + (size_t)trow * 32 + tcol + 4);

    for (int kb = 0; kb < emax; kb += TK3) {
        __syncthreads();
        *(float4*)(Ksh + trow * KST + tcol)     = kA;
        *(float4*)(Ksh + trow * KST + tcol + 4) = kB;
        *(float4*)(Vsh + trow * KST + tcol)     = vA;
        *(float4*)(Vsh + trow * KST + tcol + 4) = vB;
        if (kb + TK3 < emax) {
            kA = *(const float4*)(Kb + (size_t)(kb + TK3 + trow) * 32 + tcol);
            kB = *(const float4*)(Kb + (size_t)(kb + TK3 + trow) * 32 + tcol + 4);
            vA = *(const float4*)(Vb + (size_t)(kb + TK3 + trow) * 32 + tcol);
            vB = *(const float4*)(Vb + (size_t)(kb + TK3 + trow) * 32 + tcol + 4);
        }
        __syncthreads();
        if (kb >= wend) continue;   // this warp done; still hits barriers

        // ---- scoring: S(16q x 32k) = Q * K^T via mma, per 8-key n-tile j ----
        #pragma unroll
        for (int j = 0; j < 4; ++j) {
            float c[4] = {0.f, 0.f, 0.f, 0.f};
            const float* kr = Ksh + (8*j + g) * KST;
            #pragma unroll
            for (int s = 0; s < 4; ++s) {
                unsigned b0 = __float_as_uint(kr[8*s + tig]);
                unsigned b1 = __float_as_uint(kr[8*s + tig + 4]);
                mma_tf32(c, qa[s][0], qa[s][1], qa[s][2], qa[s][3], b0, b1);
            }
            int ke = kb + 8*j + 2*tig;
            float p0 = (ke     < endA) ? to_tf32(__expf(c[0])) : 0.f;
            float p1 = (ke + 1 < endA) ? to_tf32(__expf(c[1])) : 0.f;
            float p2 = (ke     < endB) ? to_tf32(__expf(c[2])) : 0.f;
            float p3 = (ke + 1 < endB) ? to_tf32(__expf(c[3])) : 0.f;
            su_lo += p0 + p1;
            su_hi += p2 + p3;
            int pr = (8*j + 2*tig) * PST + qbase;
            psh[pr + g]           = p0;
            psh[pr + PST + g]     = p1;
            psh[pr + g + 8]       = p2;
            psh[pr + PST + g + 8] = p3;
        }
        __syncwarp();

        // ---- PV: O^T(32d x 16q) += V^T * P^T via mma ----
        #pragma unroll
        for (int s = 0; s < 4; ++s) {
            int k0 = (8*s + tig) * PST + qbase;
            int k1 = (8*s + tig + 4) * PST + qbase;
            unsigned pb00 = __float_as_uint(psh[k0 + g]);
            unsigned pb01 = __float_as_uint(psh[k1 + g]);
            unsigned pb10 = __float_as_uint(psh[k0 + 8 + g]);
            unsigned pb11 = __float_as_uint(psh[k1 + 8 + g]);
            #pragma unroll
            for (int md = 0; md < 2; ++md) {
                const float* vr0 = Vsh + (8*s + tig) * KST + 16*md;
                const float* vr1 = Vsh + (8*s + tig + 4) * KST + 16*md;
                unsigned a0 = __float_as_uint(vr0[g]);
                unsigned a1 = __float_as_uint(vr0[g + 8]);
                unsigned a2 = __float_as_uint(vr1[g]);
                unsigned a3 = __float_as_uint(vr1[g + 8]);
                mma_tf32(o[md][0], a0, a1, a2, a3, pb00, pb01);
                mma_tf32(o[md][1], a0, a1, a2, a3, pb10, pb11);
            }
        }
    }

    // reduce denominators within each quad (over tig)
    su_lo += __shfl_xor_sync(0xffffffffu, su_lo, 1);
    su_lo += __shfl_xor_sync(0xffffffffu, su_lo, 2);
    su_hi += __shfl_xor_sync(0xffffffffu, su_hi, 1);
    su_hi += __shfl_xor_sync(0xffffffffu, su_hi, 2);

    // fetch 1/su for the query columns this thread outputs
    float inv[2][2];
    inv[0][0] = 1.f / __shfl_sync(0xffffffffu, su_lo, (2*tig)     << 2);
    inv[0][1] = 1.f / __shfl_sync(0xffffffffu, su_lo, (2*tig + 1) << 2);
    inv[1][0] = 1.f / __shfl_sync(0xffffffffu, su_hi, (2*tig)     << 2);
    inv[1][1] = 1.f / __shfl_sync(0xffffffffu, su_hi, (2*tig + 1) << 2);

    #pragma unroll
    for (int md = 0; md < 2; ++md) {
        #pragma unroll
        for (int nq = 0; nq < 2; ++nq) {
            int qloc = qbase + 8*nq + 2*tig;
            size_t base = ((size_t)b * Lc + l0 + qloc) * HIDc + h * HDc + 16*md + g;
            d_attn[base]            = o[md][nq][0] * inv[nq][0];
            d_attn[base + HIDc]     = o[md][nq][1] * inv[nq][1];
            d_attn[base + 8]        = o[md][nq][2] * inv[nq][0];
            d_attn[base + HIDc + 8] = o[md][nq][3] * inv[nq][1];
        }
    }
}

// ---------------------------------------------------------------------------
// Pool(6) [+ exact 1e-9 masked-tail term] -> o_w -> LN -> f_w -> SiLU.
#define FTOK 8
__global__ __launch_bounds__(128) void final_kernel(
    const float* __restrict__ o_w,    const float* __restrict__ o_b,
    const float* __restrict__ f_ln_w, const float* __restrict__ f_ln_b,
    const float* __restrict__ f_w,    const float* __restrict__ f_b,
    float* __restrict__ out)
{
    int p0 = blockIdx.x * FTOK;
    int c = threadIdx.x;
    int w = c >> 5, lane = c & 31;

    __shared__ float sp[FTOK][128];
    __shared__ float sln[FTOK][128];
    __shared__ float redA[FTOK][4], redB[FTOK][4];

    #pragma unroll
    for (int t = 0; t < FTOK; ++t) {
        int bt = p0 + t;
        int b = bt / Tt, tt = bt - b * Tt;
        float p = 0.0f;
        #pragma unroll
        for (int k = 0; k < Nf; ++k)
            p += d_attn[((size_t)b * Lc + tt * Nf + k) * HIDc + c];
        sp[t][c] = p * (1.0f / Nf) + 1e-9f * d_SV[((size_t)b * Tt + tt) * HIDc + c];
    }
    __syncthreads();

    float acc[FTOK];
    float ob = o_b[c];
    #pragma unroll
    for (int t = 0; t < FTOK; ++t) acc[t] = ob;
    #pragma unroll 4
    for (int dd = 0; dd < 128; ++dd) {
        float wv = o_w[dd * HIDc + c];
        #pragma unroll
        for (int t = 0; t < FTOK; ++t) acc[t] += sp[t][dd] * wv;
    }

    #pragma unroll
    for (int t = 0; t < FTOK; ++t) {
        float s = acc[t], s2 = acc[t] * acc[t];
        #pragma unroll
        for (int o = 16; o; o >>= 1) {
            s  += __shfl_xor_sync(0xffffffffu, s,  o);
            s2 += __shfl_xor_sync(0xffffffffu, s2, o);
        }
        if (lane == 0) { redA[t][w] = s; redB[t][w] = s2; }
    }
    __syncthreads();
    #pragma unroll
    for (int t = 0; t < FTOK; ++t) {
        float S  = redA[t][0] + redA[t][1] + redA[t][2] + redA[t][3];
        float S2 = redB[t][0] + redB[t][1] + redB[t][2] + redB[t][3];
        float mu  = S * (1.0f / 128.0f);
        float var = S2 * (1.0f / 128.0f) - mu * mu;
        sln[t][c] = (acc[t] - mu) * rsqrtf(var + EPSc) * f_ln_w[c] + f_ln_b[c];
    }
    __syncthreads();

    float f[FTOK];
    float fb = f_b[c];
    #pragma unroll
    for (int t = 0; t < FTOK; ++t) f[t] = fb;
    #pragma unroll 4
    for (int dd = 0; dd < 128; ++dd) {
        float wv = f_w[dd * HIDc + c];
        #pragma unroll
        for (int t = 0; t < FTOK; ++t) f[t] += sln[t][dd] * wv;
    }
    #pragma unroll
    for (int t = 0; t < FTOK; ++t) {
        float ff = f[t];
        out[(size_t)(p0 + t) * FDc + c] = ff / (1.0f + __expf(-ff));
    }
}

// ---------------------------------------------------------------------------
extern "C" void kernel_launch(void* const* d_in, const int* in_sizes, int n_in,
                              void* d_out, int out_size)
{
    const float* x      = (const float*)d_in[0];
    const float* g_ln_w = (const float*)d_in[1];
    const float* g_ln_b = (const float*)d_in[2];
    const float* g_w1   = (const float*)d_in[3];
    const float* g_b1   = (const float*)d_in[4];
    const float* g_w2   = (const float*)d_in[5];
    const float* g_b2   = (const float*)d_in[6];
    const float* q_w    = (const float*)d_in[7];
    const float* q_b    = (const float*)d_in[8];
    const float* k_w    = (const float*)d_in[9];
    const float* k_b    = (const float*)d_in[10];
    const float* v_w    = (const float*)d_in[11];
    const float* v_b    = (const float*)d_in[12];
    const float* o_w    = (const float*)d_in[13];
    const float* o_b    = (const float*)d_in[14];
    const float* f_ln_w = (const float*)d_in[15];
    const float* f_ln_b = (const float*)d_in[16];
    const float* f_w    = (const float*)d_in[17];
    const float* f_b    = (const float*)d_in[18];

    zero_tbs_kernel<<<(Bc*Tt*HIDc + 255) / 256, 256>>>();
    qkv_gate_kernel<<<(Bc * Lc) / QTOK, 128>>>(x, g_ln_w, g_ln_b, g_w1, g_b1,
                                               g_w2, g_b2, q_w, q_b, k_w, k_b,
                                               v_w, v_b);
    scan_sv_kernel<<<Bc * HIDc, Tt>>>();
    attn_kernel<<<dim3(Lc / TQ3, NHc, Bc), 128>>>();
    final_kernel<<<(Bc * Tt) / FTOK, 128>>>(o_w, o_b, f_ln_w, f_ln_b, f_w, f_b,
                                            (float*)d_out);
}

// round 4
// speedup vs baseline: 3.4107x; 1.2771x over previous
#include <cuda_runtime.h>
#include <math.h>

// Problem constants
#define Bc   2
#define Tt   512
#define Nf   6
#define Dd   32
#define HIDc 128
#define NHc  4
#define HDc  32
#define Lc   3072      // Tt*Nf
#define GHc  32
#define FDc  128
#define EPSc 1e-5f

#define NCHUNK 3
#define CHUNK  1024

// Scratch (device globals: no allocation allowed)
__device__ float d_Q[Bc*NHc*Lc*HDc];     // [b][h][l][d]  (Q pre-scaled, tf32-rounded)
__device__ float d_Kg[Bc*NHc*Lc*HDc];
__device__ float d_Vg[Bc*NHc*Lc*HDc];
__device__ float d_TBS[Bc*Tt*HIDc];      // per-time-block V sums, hid layout
__device__ float d_SV[Bc*Tt*HIDc];       // suffix sums of V beyond block t
__device__ float d_part[NCHUNK*Bc*Lc*HIDc]; // unnormalized attention partials
__device__ float d_psum[NCHUNK*Bc*NHc*Lc];  // softmax denominator partials

__device__ __forceinline__ float to_tf32(float x) {
    float r;
    asm("cvt.rna.tf32.f32 %0, %1;" : "=f"(r) : "f"(x));
    return r;
}

// D(16x8) += A(16x8,tf32) * B(8x8,tf32), fp32 accum.
__device__ __forceinline__ void mma_tf32(float c[4],
    unsigned a0, unsigned a1, unsigned a2, unsigned a3,
    unsigned b0, unsigned b1)
{
    asm volatile(
        "mma.sync.aligned.m16n8k8.row.col.f32.tf32.tf32.f32 "
        "{%0,%1,%2,%3}, {%4,%5,%6,%7}, {%8,%9}, {%0,%1,%2,%3};"
        : "+f"(c[0]), "+f"(c[1]), "+f"(c[2]), "+f"(c[3])
        : "r"(a0), "r"(a1), "r"(a2), "r"(a3), "r"(b0), "r"(b1));
}

// ---------------------------------------------------------------------------
__global__ void zero_tbs_kernel() {
    int i = blockIdx.x * blockDim.x + threadIdx.x;
    if (i < Bc*Tt*HIDc) d_TBS[i] = 0.0f;
}

// ---------------------------------------------------------------------------
// Fused gater + gated QKV. One block (128 threads) per 8 tokens.
#define QTOK 8
__global__ __launch_bounds__(128) void qkv_gate_kernel(const float* __restrict__ x,
    const float* __restrict__ g_ln_w, const float* __restrict__ g_ln_b,
    const float* __restrict__ g_w1,   const float* __restrict__ g_b1,
    const float* __restrict__ g_w2,   const float* __restrict__ g_b2,
    const float* __restrict__ q_w,    const float* __restrict__ q_b,
    const float* __restrict__ k_w,    const float* __restrict__ k_b,
    const float* __restrict__ v_w,    const float* __restrict__ v_b)
{
    const float SC = 0.17677669529663688f;  // 1/sqrt(32)
    int t0 = blockIdx.x * QTOK;
    int tid = threadIdx.x;
    int w = tid >> 5, lane = tid & 31;

    __shared__ float xs[QTOK][32];
    __shared__ float gate[QTOK];

    #pragma unroll
    for (int i = tid; i < QTOK*32; i += 128)
        xs[i >> 5][i & 31] = x[(size_t)t0 * 32 + i];
    __syncthreads();

    #pragma unroll
    for (int kk = 0; kk < 2; ++kk) {
        int t = w * 2 + kk;
        float xv = xs[t][lane];
        float s = xv, s2 = xv * xv;
        #pragma unroll
        for (int o = 16; o; o >>= 1) {
            s  += __shfl_xor_sync(0xffffffffu, s,  o);
            s2 += __shfl_xor_sync(0xffffffffu, s2, o);
        }
        float mu  = s * (1.0f / 32.0f);
        float var = s2 * (1.0f / 32.0f) - mu * mu;
        float xn = (xv - mu) * rsqrtf(var + EPSc) * g_ln_w[lane] + g_ln_b[lane];
        float h = g_b1[lane];
        #pragma unroll
        for (int d = 0; d < 32; ++d)
            h += __shfl_sync(0xffffffffu, xn, d) * g_w1[d * GHc + lane];
        h = h / (1.0f + __expf(-h));
        float gp = h * g_w2[lane];
        #pragma unroll
        for (int o = 16; o; o >>= 1) gp += __shfl_xor_sync(0xffffffffu, gp, o);
        if (lane == 0) gate[t] = 1.0f / (1.0f + __expf(-(gp + g_b2[0])));
    }
    __syncthreads();

    int c = tid;
    float q[QTOK], k[QTOK], v[QTOK];
    float qb = q_b[c], kb = k_b[c], vb = v_b[c];
    #pragma unroll
    for (int t = 0; t < QTOK; ++t) { q[t] = qb; k[t] = kb; v[t] = vb; }
    #pragma unroll
    for (int dd = 0; dd < 32; ++dd) {
        float wq = q_w[dd * HIDc + c];
        float wk = k_w[dd * HIDc + c];
        float wv = v_w[dd * HIDc + c];
        #pragma unroll
        for (int t = 0; t < QTOK; ++t) {
            float xd = xs[t][dd];
            q[t] += xd * wq; k[t] += xd * wk; v[t] += xd * wv;
        }
    }

    int hh = c >> 5, d2 = c & 31;
    #pragma unroll
    for (int t = 0; t < QTOK; ++t) {
        int token = t0 + t;
        int b = token / Lc, l = token - b * Lc;
        float g = gate[t];
        size_t idx = ((size_t)(b * NHc + hh) * Lc + l) * HDc + d2;
        d_Q[idx]  = to_tf32(q[t] * g * SC);
        d_Kg[idx] = to_tf32(k[t] * g);
        float vg = to_tf32(v[t] * g);
        d_Vg[idx] = vg;
        atomicAdd(&d_TBS[((size_t)b * Tt + l / Nf) * HIDc + c], vg);
    }
}

// ---------------------------------------------------------------------------
// Parallel suffix scan: SV[b][t][c] = sum over time blocks > t of TBS.
__global__ void scan_sv_kernel() {
    int col = blockIdx.x;
    int b = col >> 7, c = col & 127;
    int t = threadIdx.x;
    __shared__ float sh[Tt];
    size_t idx = ((size_t)b * Tt + t) * HIDc + c;
    float val = d_TBS[idx];
    sh[t] = val;
    __syncthreads();
    #pragma unroll
    for (int off = 1; off < Tt; off <<= 1) {
        float add = (t + off < Tt) ? sh[t + off] : 0.0f;
        __syncthreads();
        sh[t] += add;
        __syncthreads();
    }
    d_SV[idx] = sh[t] - val;   // exclusive suffix sum
}

// ---------------------------------------------------------------------------
// Tensor-core (tf32 mma.sync) block-causal attention, split-K over 1024-key
// chunks (additive partials; no online max needed since p=exp(s) directly).
// 128 threads, 4 warps x 16 queries = 64 queries/CTA, 32-key tiles.
// grid.x = 98: ids [0,48) chunk0, [48,81) chunk1 (bx 0..32), [81,98) chunk2 (bx 0..16).
#define TQ3 64
#define TK3 32
#define KST 36   // K/V smem row stride (floats)
#define PST 68   // psh row stride (floats)
__global__ __launch_bounds__(128) void attn_kernel()
{
    int id = blockIdx.x;                     // 0..97
    int bx, chunk;
    if (id < 48)      { bx = id;      chunk = 0; }
    else if (id < 81) { bx = id - 48; chunk = 1; }
    else              { bx = id - 81; chunk = 2; }
    int h  = blockIdx.y;
    int b  = blockIdx.z;
    int l0 = Lc - TQ3 * (bx + 1);            // longest-work blocks first
    int bh = b * NHc + h;

    const float* Qb = d_Q  + (size_t)bh * Lc * HDc;
    const float* Kb = d_Kg + (size_t)bh * Lc * HDc;
    const float* Vb = d_Vg + (size_t)bh * Lc * HDc;
    float* partp = d_part + (size_t)chunk * (Bc*Lc*HIDc);

    __shared__ __align__(16) float Ksh[TK3 * KST];
    __shared__ __align__(16) float Vsh[TK3 * KST];
    __shared__ __align__(16) float psh[TK3 * PST];  // P^T: [key][64 queries]

    int tid  = threadIdx.x;
    int w    = tid >> 5;
    int lane = tid & 31;
    int g    = lane >> 2;        // groupID
    int tig  = lane & 3;         // thread-in-group
    int qbase = w * 16;

    // Q A-fragments (per k-step s: dims 8s..8s+7), held in registers
    unsigned qa[4][4];
    const float* Qp = Qb + (size_t)(l0 + qbase) * 32;
    #pragma unroll
    for (int s = 0; s < 4; ++s) {
        qa[s][0] = __float_as_uint(Qp[(size_t)g * 32 + 8*s + tig]);
        qa[s][1] = __float_as_uint(Qp[(size_t)(g + 8) * 32 + 8*s + tig]);
        qa[s][2] = __float_as_uint(Qp[(size_t)g * 32 + 8*s + tig + 4]);
        qa[s][3] = __float_as_uint(Qp[(size_t)(g + 8) * 32 + 8*s + tig + 4]);
    }

    int endA = 6 * ((l0 + qbase + g) / 6) + 6;        // causal end, row g
    int endB = 6 * ((l0 + qbase + g + 8) / 6) + 6;    // causal end, row g+8
    int wend = 6 * ((l0 + qbase + 15) / 6) + 6;       // warp's max end
    int emax = 6 * ((l0 + TQ3 - 1) / 6) + 6;          // CTA's max end

    int kstart = chunk * CHUNK;
    int kend   = min(emax, kstart + CHUNK);           // CTA's chunk range

    float o[2][2][4] = {};       // O^T accum [md][nq][reg]
    float su_lo = 0.f, su_hi = 0.f;

    // tile loader mapping: 128 thr -> 32 rows x (8 floats each)
    int trow = tid >> 2;
    int tcol = (tid & 3) * 8;

    float4 kA = *(const float4*)(Kb + (size_t)(kstart + trow) * 32 + tcol);
    float4 kB = *(const float4*)(Kb + (size_t)(kstart + trow) * 32 + tcol + 4);
    float4 vA = *(const float4*)(Vb + (size_t)(kstart + trow) * 32 + tcol);
    float4 vB = *(const float4*)(Vb + (size_t)(kstart + trow) * 32 + tcol + 4);

    for (int kb = kstart; kb < kend; kb += TK3) {
        __syncthreads();
        *(float4*)(Ksh + trow * KST + tcol)     = kA;
        *(float4*)(Ksh + trow * KST + tcol + 4) = kB;
        *(float4*)(Vsh + trow * KST + tcol)     = vA;
        *(float4*)(Vsh + trow * KST + tcol + 4) = vB;
        if (kb + TK3 < kend) {
            kA = *(const float4*)(Kb + (size_t)(kb + TK3 + trow) * 32 + tcol);
            kB = *(const float4*)(Kb + (size_t)(kb + TK3 + trow) * 32 + tcol + 4);
            vA = *(const float4*)(Vb + (size_t)(kb + TK3 + trow) * 32 + tcol);
            vB = *(const float4*)(Vb + (size_t)(kb + TK3 + trow) * 32 + tcol + 4);
        }
        __syncthreads();
        if (kb >= wend) continue;   // this warp done; still hits barriers

        // ---- scoring: S(16q x 32k) = Q * K^T via mma, per 8-key n-tile j ----
        #pragma unroll
        for (int j = 0; j < 4; ++j) {
            float c[4] = {0.f, 0.f, 0.f, 0.f};
            const float* kr = Ksh + (8*j + g) * KST;
            #pragma unroll
            for (int s = 0; s < 4; ++s) {
                unsigned b0 = __float_as_uint(kr[8*s + tig]);
                unsigned b1 = __float_as_uint(kr[8*s + tig + 4]);
                mma_tf32(c, qa[s][0], qa[s][1], qa[s][2], qa[s][3], b0, b1);
            }
            int ke = kb + 8*j + 2*tig;
            float p0 = (ke     < endA) ? to_tf32(__expf(c[0])) : 0.f;
            float p1 = (ke + 1 < endA) ? to_tf32(__expf(c[1])) : 0.f;
            float p2 = (ke     < endB) ? to_tf32(__expf(c[2])) : 0.f;
            float p3 = (ke + 1 < endB) ? to_tf32(__expf(c[3])) : 0.f;
            su_lo += p0 + p1;
            su_hi += p2 + p3;
            int pr = (8*j + 2*tig) * PST + qbase;
            psh[pr + g]           = p0;
            psh[pr + PST + g]     = p1;
            psh[pr + g + 8]       = p2;
            psh[pr + PST + g + 8] = p3;
        }
        __syncwarp();

        // ---- PV: O^T(32d x 16q) += V^T * P^T via mma ----
        #pragma unroll
        for (int s = 0; s < 4; ++s) {
            int k0 = (8*s + tig) * PST + qbase;
            int k1 = (8*s + tig + 4) * PST + qbase;
            unsigned pb00 = __float_as_uint(psh[k0 + g]);
            unsigned pb01 = __float_as_uint(psh[k1 + g]);
            unsigned pb10 = __float_as_uint(psh[k0 + 8 + g]);
            unsigned pb11 = __float_as_uint(psh[k1 + 8 + g]);
            #pragma unroll
            for (int md = 0; md < 2; ++md) {
                const float* vr0 = Vsh + (8*s + tig) * KST + 16*md;
                const float* vr1 = Vsh + (8*s + tig + 4) * KST + 16*md;
                unsigned a0 = __float_as_uint(vr0[g]);
                unsigned a1 = __float_as_uint(vr0[g + 8]);
                unsigned a2 = __float_as_uint(vr1[g]);
                unsigned a3 = __float_as_uint(vr1[g + 8]);
                mma_tf32(o[md][0], a0, a1, a2, a3, pb00, pb01);
                mma_tf32(o[md][1], a0, a1, a2, a3, pb10, pb11);
            }
        }
    }

    // reduce denominator partials within each quad (over tig)
    su_lo += __shfl_xor_sync(0xffffffffu, su_lo, 1);
    su_lo += __shfl_xor_sync(0xffffffffu, su_lo, 2);
    su_hi += __shfl_xor_sync(0xffffffffu, su_hi, 1);
    su_hi += __shfl_xor_sync(0xffffffffu, su_hi, 2);
    if (tig == 0) {
        size_t sb = (size_t)chunk * (Bc*NHc*Lc) + (size_t)bh * Lc + l0 + qbase;
        d_psum[sb + g]     = su_lo;
        d_psum[sb + g + 8] = su_hi;
    }

    #pragma unroll
    for (int md = 0; md < 2; ++md) {
        #pragma unroll
        for (int nq = 0; nq < 2; ++nq) {
            int qloc = qbase + 8*nq + 2*tig;
            size_t base = ((size_t)b * Lc + l0 + qloc) * HIDc + h * HDc + 16*md + g;
            partp[base]            = o[md][nq][0];
            partp[base + HIDc]     = o[md][nq][1];
            partp[base + 8]        = o[md][nq][2];
            partp[base + HIDc + 8] = o[md][nq][3];
        }
    }
}

// ---------------------------------------------------------------------------
// Combine split-K partials + pool(6) + exact 1e-9 masked tail -> o_w -> LN
// -> f_w -> SiLU.  8 (b,t) rows per block.
#define FTOK 8
__global__ __launch_bounds__(128) void final_kernel(
    const float* __restrict__ o_w,    const float* __restrict__ o_b,
    const float* __restrict__ f_ln_w, const float* __restrict__ f_ln_b,
    const float* __restrict__ f_w,    const float* __restrict__ f_b,
    float* __restrict__ out)
{
    int p0 = blockIdx.x * FTOK;
    int c = threadIdx.x;
    int w = c >> 5, lane = c & 31;
    int h = c >> 5;

    __shared__ float sp[FTOK][128];
    __shared__ float sln[FTOK][128];
    __shared__ float redA[FTOK][4], redB[FTOK][4];

    #pragma unroll
    for (int t = 0; t < FTOK; ++t) {
        int bt = p0 + t;
        int b = bt / Tt, tt = bt - b * Tt;
        int end = tt * Nf + Nf;
        int nc = (end + CHUNK - 1) >> 10;    // live chunks: ceil(end/1024)
        float p = 0.0f;
        #pragma unroll
        for (int k = 0; k < Nf; ++k) {
            int l = tt * Nf + k;
            float su = 0.f, oo = 0.f;
            for (int cc = 0; cc < nc; ++cc) {
                su += d_psum[(size_t)cc * (Bc*NHc*Lc) + ((size_t)b*NHc + h)*Lc + l];
                oo += d_part[(size_t)cc * (Bc*Lc*HIDc) + ((size_t)b*Lc + l)*HIDc + c];
            }
            p += oo / su;
        }
        sp[t][c] = p * (1.0f / Nf) + 1e-9f * d_SV[((size_t)b * Tt + tt) * HIDc + c];
    }
    __syncthreads();

    float acc[FTOK];
    float ob = o_b[c];
    #pragma unroll
    for (int t = 0; t < FTOK; ++t) acc[t] = ob;
    #pragma unroll 4
    for (int dd = 0; dd < 128; ++dd) {
        float wv = o_w[dd * HIDc + c];
        #pragma unroll
        for (int t = 0; t < FTOK; ++t) acc[t] += sp[t][dd] * wv;
    }

    #pragma unroll
    for (int t = 0; t < FTOK; ++t) {
        float s = acc[t], s2 = acc[t] * acc[t];
        #pragma unroll
        for (int o = 16; o; o >>= 1) {
            s  += __shfl_xor_sync(0xffffffffu, s,  o);
            s2 += __shfl_xor_sync(0xffffffffu, s2, o);
        }
        if (lane == 0) { redA[t][w] = s; redB[t][w] = s2; }
    }
    __syncthreads();
    #pragma unroll
    for (int t = 0; t < FTOK; ++t) {
        float S  = redA[t][0] + redA[t][1] + redA[t][2] + redA[t][3];
        float S2 = redB[t][0] + redB[t][1] + redB[t][2] + redB[t][3];
        float mu  = S * (1.0f / 128.0f);
        float var = S2 * (1.0f / 128.0f) - mu * mu;
        sln[t][c] = (acc[t] - mu) * rsqrtf(var + EPSc) * f_ln_w[c] + f_ln_b[c];
    }
    __syncthreads();

    float f[FTOK];
    float fb = f_b[c];
    #pragma unroll
    for (int t = 0; t < FTOK; ++t) f[t] = fb;
    #pragma unroll 4
    for (int dd = 0; dd < 128; ++dd) {
        float wv = f_w[dd * HIDc + c];
        #pragma unroll
        for (int t = 0; t < FTOK; ++t) f[t] += sln[t][dd] * wv;
    }
    #pragma unroll
    for (int t = 0; t < FTOK; ++t) {
        float ff = f[t];
        out[(size_t)(p0 + t) * FDc + c] = ff / (1.0f + __expf(-ff));
    }
}

// ---------------------------------------------------------------------------
extern "C" void kernel_launch(void* const* d_in, const int* in_sizes, int n_in,
                              void* d_out, int out_size)
{
    const float* x      = (const float*)d_in[0];
    const float* g_ln_w = (const float*)d_in[1];
    const float* g_ln_b = (const float*)d_in[2];
    const float* g_w1   = (const float*)d_in[3];
    const float* g_b1   = (const float*)d_in[4];
    const float* g_w2   = (const float*)d_in[5];
    const float* g_b2   = (const float*)d_in[6];
    const float* q_w    = (const float*)d_in[7];
    const float* q_b    = (const float*)d_in[8];
    const float* k_w    = (const float*)d_in[9];
    const float* k_b    = (const float*)d_in[10];
    const float* v_w    = (const float*)d_in[11];
    const float* v_b    = (const float*)d_in[12];
    const float* o_w    = (const float*)d_in[13];
    const float* o_b    = (const float*)d_in[14];
    const float* f_ln_w = (const float*)d_in[15];
    const float* f_ln_b = (const float*)d_in[16];
    const float* f_w    = (const float*)d_in[17];
    const float* f_b    = (const float*)d_in[18];

    zero_tbs_kernel<<<(Bc*Tt*HIDc + 255) / 256, 256>>>();
    qkv_gate_kernel<<<(Bc * Lc) / QTOK, 128>>>(x, g_ln_w, g_ln_b, g_w1, g_b1,
                                               g_w2, g_b2, q_w, q_b, k_w, k_b,
                                               v_w, v_b);
    scan_sv_kernel<<<Bc * HIDc, Tt>>>();
    attn_kernel<<<dim3(98, NHc, Bc), 128>>>();
    final_kernel<<<(Bc * Tt) / FTOK, 128>>>(o_w, o_b, f_ln_w, f_ln_b, f_w, f_b,
                                            (float*)d_out);
}

// round 5
// speedup vs baseline: 3.6347x; 1.0657x over previous
#include <cuda_runtime.h>
#include <cuda_fp16.h>
#include <math.h>

// Problem constants
#define Bc   2
#define Tt   512
#define Nf   6
#define Dd   32
#define HIDc 128
#define NHc  4
#define HDc  32
#define Lc   3072      // Tt*Nf
#define GHc  32
#define FDc  128
#define EPSc 1e-5f

#define NCHUNK 6
#define CHUNK  512

// Scratch (device globals: no allocation allowed)
__device__ __half d_Qh[Bc*NHc*Lc*HDc];   // fp16 Q (pre-scaled by 1/sqrt(HD))
__device__ __half d_Kh[Bc*NHc*Lc*HDc];   // fp16 K
__device__ float  d_Vg[Bc*NHc*Lc*HDc];   // fp32 (tf32-rounded) V
__device__ float  d_TBS[Bc*Tt*HIDc];     // per-time-block V sums, hid layout
__device__ float  d_SV[Bc*Tt*HIDc];      // suffix sums of V beyond block t
__device__ float  d_part[NCHUNK*Bc*Lc*HIDc]; // unnormalized attention partials
__device__ float  d_psum[NCHUNK*Bc*NHc*Lc];  // softmax denominator partials

__device__ __forceinline__ float to_tf32(float x) {
    float r;
    asm("cvt.rna.tf32.f32 %0, %1;" : "=f"(r) : "f"(x));
    return r;
}

// D(16x8) += A(16x8,tf32) * B(8x8,tf32), fp32 accum.
__device__ __forceinline__ void mma_tf32(float c[4],
    unsigned a0, unsigned a1, unsigned a2, unsigned a3,
    unsigned b0, unsigned b1)
{
    asm volatile(
        "mma.sync.aligned.m16n8k8.row.col.f32.tf32.tf32.f32 "
        "{%0,%1,%2,%3}, {%4,%5,%6,%7}, {%8,%9}, {%0,%1,%2,%3};"
        : "+f"(c[0]), "+f"(c[1]), "+f"(c[2]), "+f"(c[3])
        : "r"(a0), "r"(a1), "r"(a2), "r"(a3), "r"(b0), "r"(b1));
}

// D(16x8) += A(16x16,f16) * B(16x8,f16), fp32 accum.
__device__ __forceinline__ void mma_f16(float c[4],
    unsigned a0, unsigned a1, unsigned a2, unsigned a3,
    unsigned b0, unsigned b1)
{
    asm volatile(
        "mma.sync.aligned.m16n8k16.row.col.f32.f16.f16.f32 "
        "{%0,%1,%2,%3}, {%4,%5,%6,%7}, {%8,%9}, {%0,%1,%2,%3};"
        : "+f"(c[0]), "+f"(c[1]), "+f"(c[2]), "+f"(c[3])
        : "r"(a0), "r"(a1), "r"(a2), "r"(a3), "r"(b0), "r"(b1));
}

// ---------------------------------------------------------------------------
__global__ void zero_tbs_kernel() {
    int i = blockIdx.x * blockDim.x + threadIdx.x;
    if (i < Bc*Tt*HIDc) d_TBS[i] = 0.0f;
}

// ---------------------------------------------------------------------------
// Fused gater + gated QKV. One block (128 threads) per 8 tokens.
#define QTOK 8
__global__ __launch_bounds__(128) void qkv_gate_kernel(const float* __restrict__ x,
    const float* __restrict__ g_ln_w, const float* __restrict__ g_ln_b,
    const float* __restrict__ g_w1,   const float* __restrict__ g_b1,
    const float* __restrict__ g_w2,   const float* __restrict__ g_b2,
    const float* __restrict__ q_w,    const float* __restrict__ q_b,
    const float* __restrict__ k_w,    const float* __restrict__ k_b,
    const float* __restrict__ v_w,    const float* __restrict__ v_b)
{
    const float SC = 0.17677669529663688f;  // 1/sqrt(32)
    int t0 = blockIdx.x * QTOK;
    int tid = threadIdx.x;
    int w = tid >> 5, lane = tid & 31;

    __shared__ float xs[QTOK][32];
    __shared__ float gate[QTOK];

    #pragma unroll
    for (int i = tid; i < QTOK*32; i += 128)
        xs[i >> 5][i & 31] = x[(size_t)t0 * 32 + i];
    __syncthreads();

    #pragma unroll
    for (int kk = 0; kk < 2; ++kk) {
        int t = w * 2 + kk;
        float xv = xs[t][lane];
        float s = xv, s2 = xv * xv;
        #pragma unroll
        for (int o = 16; o; o >>= 1) {
            s  += __shfl_xor_sync(0xffffffffu, s,  o);
            s2 += __shfl_xor_sync(0xffffffffu, s2, o);
        }
        float mu  = s * (1.0f / 32.0f);
        float var = s2 * (1.0f / 32.0f) - mu * mu;
        float xn = (xv - mu) * rsqrtf(var + EPSc) * g_ln_w[lane] + g_ln_b[lane];
        float h = g_b1[lane];
        #pragma unroll
        for (int d = 0; d < 32; ++d)
            h += __shfl_sync(0xffffffffu, xn, d) * g_w1[d * GHc + lane];
        h = h / (1.0f + __expf(-h));
        float gp = h * g_w2[lane];
        #pragma unroll
        for (int o = 16; o; o >>= 1) gp += __shfl_xor_sync(0xffffffffu, gp, o);
        if (lane == 0) gate[t] = 1.0f / (1.0f + __expf(-(gp + g_b2[0])));
    }
    __syncthreads();

    int c = tid;
    float q[QTOK], k[QTOK], v[QTOK];
    float qb = q_b[c], kb = k_b[c], vb = v_b[c];
    #pragma unroll
    for (int t = 0; t < QTOK; ++t) { q[t] = qb; k[t] = kb; v[t] = vb; }
    #pragma unroll
    for (int dd = 0; dd < 32; ++dd) {
        float wq = q_w[dd * HIDc + c];
        float wk = k_w[dd * HIDc + c];
        float wv = v_w[dd * HIDc + c];
        #pragma unroll
        for (int t = 0; t < QTOK; ++t) {
            float xd = xs[t][dd];
            q[t] += xd * wq; k[t] += xd * wk; v[t] += xd * wv;
        }
    }

    int hh = c >> 5, d2 = c & 31;
    #pragma unroll
    for (int t = 0; t < QTOK; ++t) {
        int token = t0 + t;
        int b = token / Lc, l = token - b * Lc;
        float g = gate[t];
        size_t idx = ((size_t)(b * NHc + hh) * Lc + l) * HDc + d2;
        d_Qh[idx] = __float2half_rn(q[t] * g * SC);
        d_Kh[idx] = __float2half_rn(k[t] * g);
        float vg = to_tf32(v[t] * g);
        d_Vg[idx] = vg;
        atomicAdd(&d_TBS[((size_t)b * Tt + l / Nf) * HIDc + c], vg);
    }
}

// ---------------------------------------------------------------------------
// Parallel suffix scan: SV[b][t][c] = sum over time blocks > t of TBS.
__global__ void scan_sv_kernel() {
    int col = blockIdx.x;
    int b = col >> 7, c = col & 127;
    int t = threadIdx.x;
    __shared__ float sh[Tt];
    size_t idx = ((size_t)b * Tt + t) * HIDc + c;
    float val = d_TBS[idx];
    sh[t] = val;
    __syncthreads();
    #pragma unroll
    for (int off = 1; off < Tt; off <<= 1) {
        float add = (t + off < Tt) ? sh[t + off] : 0.0f;
        __syncthreads();
        sh[t] += add;
        __syncthreads();
    }
    d_SV[idx] = sh[t] - val;   // exclusive suffix sum
}

// ---------------------------------------------------------------------------
// Tensor-core block-causal attention: fp16 scoring mma + tf32 PV mma,
// split-K over 512-key chunks (additive partials; p=exp(s), no online max).
// 128 threads, 4 warps x 16 queries = 64 queries/CTA, 32-key tiles.
#define TQ3 64
#define TK3 32
#define KSTH 40  // K smem row stride (halves)
#define KST 36   // V smem row stride (floats)
#define PST 68   // psh row stride (floats)
__global__ __launch_bounds__(128, 6) void attn_kernel()
{
    // map blockIdx.x -> (qtile bx, key chunk)
    int id = blockIdx.x;
    int bx = 0, l0, emax;
    for (;;) {
        l0 = Lc - TQ3 * (bx + 1);
        emax = 6 * ((l0 + TQ3 - 1) / 6) + 6;
        int nch = (emax + CHUNK - 1) / CHUNK;
        if (id < nch) break;
        id -= nch; ++bx;
    }
    int chunk = id;
    int h  = blockIdx.y;
    int b  = blockIdx.z;
    int bh = b * NHc + h;

    const __half* Qb = d_Qh + (size_t)bh * Lc * HDc;
    const __half* Kb = d_Kh + (size_t)bh * Lc * HDc;
    const float*  Vb = d_Vg + (size_t)bh * Lc * HDc;
    float* partp = d_part + (size_t)chunk * (Bc*Lc*HIDc);

    __shared__ __align__(16) __half Ksh[TK3 * KSTH];
    __shared__ __align__(16) float  Vsh[TK3 * KST];
    __shared__ __align__(16) float  psh[TK3 * PST];  // P^T: [key][64 queries]

    int tid  = threadIdx.x;
    int w    = tid >> 5;
    int lane = tid & 31;
    int g    = lane >> 2;        // groupID
    int tig  = lane & 3;         // thread-in-group
    int qbase = w * 16;

    // Q A-fragments (fp16, k16 steps s=0,1), held in registers
    unsigned qa[2][4];
    const __half* Qp = Qb + (size_t)(l0 + qbase) * 32;
    #pragma unroll
    for (int s = 0; s < 2; ++s) {
        qa[s][0] = *(const unsigned*)(Qp + (size_t)g * 32 + 16*s + 2*tig);
        qa[s][1] = *(const unsigned*)(Qp + (size_t)(g + 8) * 32 + 16*s + 2*tig);
        qa[s][2] = *(const unsigned*)(Qp + (size_t)g * 32 + 16*s + 2*tig + 8);
        qa[s][3] = *(const unsigned*)(Qp + (size_t)(g + 8) * 32 + 16*s + 2*tig + 8);
    }

    int endA = 6 * ((l0 + qbase + g) / 6) + 6;        // causal end, row g
    int endB = 6 * ((l0 + qbase + g + 8) / 6) + 6;    // causal end, row g+8
    int wend = 6 * ((l0 + qbase + 15) / 6) + 6;       // warp's max end

    int kstart = chunk * CHUNK;
    int kend   = min(emax, kstart + CHUNK);           // CTA's chunk range

    float o[2][2][4] = {};       // O^T accum [md][nq][reg]
    float su_lo = 0.f, su_hi = 0.f;

    // tile loader mapping: 128 thr -> 32 rows x (8 elements each)
    int trow = tid >> 2;
    int tcol = (tid & 3) * 8;

    uint4  kA = *(const uint4*)(Kb + (size_t)(kstart + trow) * 32 + tcol);
    float4 vA = *(const float4*)(Vb + (size_t)(kstart + trow) * 32 + tcol);
    float4 vB = *(const float4*)(Vb + (size_t)(kstart + trow) * 32 + tcol + 4);

    for (int kb = kstart; kb < kend; kb += TK3) {
        __syncthreads();
        *(uint4*)(Ksh + trow * KSTH + tcol)     = kA;
        *(float4*)(Vsh + trow * KST + tcol)     = vA;
        *(float4*)(Vsh + trow * KST + tcol + 4) = vB;
        if (kb + TK3 < kend) {
            kA = *(const uint4*)(Kb + (size_t)(kb + TK3 + trow) * 32 + tcol);
            vA = *(const float4*)(Vb + (size_t)(kb + TK3 + trow) * 32 + tcol);
            vB = *(const float4*)(Vb + (size_t)(kb + TK3 + trow) * 32 + tcol + 4);
        }
        __syncthreads();
        if (kb >= wend) continue;   // this warp done; still hits barriers

        // ---- scoring: S(16q x 32k) = Q * K^T via fp16 mma, per 8-key tile j ----
        #pragma unroll
        for (int j = 0; j < 4; ++j) {
            float c[4] = {0.f, 0.f, 0.f, 0.f};
            const __half* kr = Ksh + (8*j + g) * KSTH;
            #pragma unroll
            for (int s = 0; s < 2; ++s) {
                unsigned b0 = *(const unsigned*)(kr + 16*s + 2*tig);
                unsigned b1 = *(const unsigned*)(kr + 16*s + 2*tig + 8);
                mma_f16(c, qa[s][0], qa[s][1], qa[s][2], qa[s][3], b0, b1);
            }
            int ke = kb + 8*j + 2*tig;
            float p0 = (ke     < endA) ? to_tf32(__expf(c[0])) : 0.f;
            float p1 = (ke + 1 < endA) ? to_tf32(__expf(c[1])) : 0.f;
            float p2 = (ke     < endB) ? to_tf32(__expf(c[2])) : 0.f;
            float p3 = (ke + 1 < endB) ? to_tf32(__expf(c[3])) : 0.f;
            su_lo += p0 + p1;
            su_hi += p2 + p3;
            int pr = (8*j + 2*tig) * PST + qbase;
            psh[pr + g]           = p0;
            psh[pr + PST + g]     = p1;
            psh[pr + g + 8]       = p2;
            psh[pr + PST + g + 8] = p3;
        }
        __syncwarp();

        // ---- PV: O^T(32d x 16q) += V^T * P^T via tf32 mma ----
        #pragma unroll
        for (int s = 0; s < 4; ++s) {
            int k0 = (8*s + tig) * PST + qbase;
            int k1 = (8*s + tig + 4) * PST + qbase;
            unsigned pb00 = __float_as_uint(psh[k0 + g]);
            unsigned pb01 = __float_as_uint(psh[k1 + g]);
            unsigned pb10 = __float_as_uint(psh[k0 + 8 + g]);
            unsigned pb11 = __float_as_uint(psh[k1 + 8 + g]);
            #pragma unroll
            for (int md = 0; md < 2; ++md) {
                const float* vr0 = Vsh + (8*s + tig) * KST + 16*md;
                const float* vr1 = Vsh + (8*s + tig + 4) * KST + 16*md;
                unsigned a0 = __float_as_uint(vr0[g]);
                unsigned a1 = __float_as_uint(vr0[g + 8]);
                unsigned a2 = __float_as_uint(vr1[g]);
                unsigned a3 = __float_as_uint(vr1[g + 8]);
                mma_tf32(o[md][0], a0, a1, a2, a3, pb00, pb01);
                mma_tf32(o[md][1], a0, a1, a2, a3, pb10, pb11);
            }
        }
    }

    // reduce denominator partials within each quad (over tig)
    su_lo += __shfl_xor_sync(0xffffffffu, su_lo, 1);
    su_lo += __shfl_xor_sync(0xffffffffu, su_lo, 2);
    su_hi += __shfl_xor_sync(0xffffffffu, su_hi, 1);
    su_hi += __shfl_xor_sync(0xffffffffu, su_hi, 2);
    if (tig == 0) {
        size_t sb = (size_t)chunk * (Bc*NHc*Lc) + (size_t)bh * Lc + l0 + qbase;
        d_psum[sb + g]     = su_lo;
        d_psum[sb + g + 8] = su_hi;
    }

    #pragma unroll
    for (int md = 0; md < 2; ++md) {
        #pragma unroll
        for (int nq = 0; nq < 2; ++nq) {
            int qloc = qbase + 8*nq + 2*tig;
            size_t base = ((size_t)b * Lc + l0 + qloc) * HIDc + h * HDc + 16*md + g;
            partp[base]            = o[md][nq][0];
            partp[base + HIDc]     = o[md][nq][1];
            partp[base + 8]        = o[md][nq][2];
            partp[base + HIDc + 8] = o[md][nq][3];
        }
    }
}

// ---------------------------------------------------------------------------
// Combine split-K partials + pool(6) + exact 1e-9 masked tail -> o_w -> LN
// -> f_w -> SiLU.  8 (b,t) rows per block.
#define FTOK 8
__global__ __launch_bounds__(128) void final_kernel(
    const float* __restrict__ o_w,    const float* __restrict__ o_b,
    const float* __restrict__ f_ln_w, const float* __restrict__ f_ln_b,
    const float* __restrict__ f_w,    const float* __restrict__ f_b,
    float* __restrict__ out)
{
    int p0 = blockIdx.x * FTOK;
    int c = threadIdx.x;
    int w = c >> 5, lane = c & 31;
    int h = c >> 5;

    __shared__ float sp[FTOK][128];
    __shared__ float sln[FTOK][128];
    __shared__ float redA[FTOK][4], redB[FTOK][4];

    #pragma unroll
    for (int t = 0; t < FTOK; ++t) {
        int bt = p0 + t;
        int b = bt / Tt, tt = bt - b * Tt;
        int end = tt * Nf + Nf;
        int nc = (end + CHUNK - 1) / CHUNK;  // live chunks
        float p = 0.0f;
        #pragma unroll
        for (int k = 0; k < Nf; ++k) {
            int l = tt * Nf + k;
            float su = 0.f, oo = 0.f;
            for (int cc = 0; cc < nc; ++cc) {
                su += d_psum[(size_t)cc * (Bc*NHc*Lc) + ((size_t)b*NHc + h)*Lc + l];
                oo += d_part[(size_t)cc * (Bc*Lc*HIDc) + ((size_t)b*Lc + l)*HIDc + c];
            }
            p += oo / su;
        }
        sp[t][c] = p * (1.0f / Nf) + 1e-9f * d_SV[((size_t)b * Tt + tt) * HIDc + c];
    }
    __syncthreads();

    float acc[FTOK];
    float ob = o_b[c];
    #pragma unroll
    for (int t = 0; t < FTOK; ++t) acc[t] = ob;
    #pragma unroll 4
    for (int dd = 0; dd < 128; ++dd) {
        float wv = o_w[dd * HIDc + c];
        #pragma unroll
        for (int t = 0; t < FTOK; ++t) acc[t] += sp[t][dd] * wv;
    }

    #pragma unroll
    for (int t = 0; t < FTOK; ++t) {
        float s = acc[t], s2 = acc[t] * acc[t];
        #pragma unroll
        for (int o = 16; o; o >>= 1) {
            s  += __shfl_xor_sync(0xffffffffu, s,  o);
            s2 += __shfl_xor_sync(0xffffffffu, s2, o);
        }
        if (lane == 0) { redA[t][w] = s; redB[t][w] = s2; }
    }
    __syncthreads();
    #pragma unroll
    for (int t = 0; t < FTOK; ++t) {
        float S  = redA[t][0] + redA[t][1] + redA[t][2] + redA[t][3];
        float S2 = redB[t][0] + redB[t][1] + redB[t][2] + redB[t][3];
        float mu  = S * (1.0f / 128.0f);
        float var = S2 * (1.0f / 128.0f) - mu * mu;
        sln[t][c] = (acc[t] - mu) * rsqrtf(var + EPSc) * f_ln_w[c] + f_ln_b[c];
    }
    __syncthreads();

    float f[FTOK];
    float fb = f_b[c];
    #pragma unroll
    for (int t = 0; t < FTOK; ++t) f[t] = fb;
    #pragma unroll 4
    for (int dd = 0; dd < 128; ++dd) {
        float wv = f_w[dd * HIDc + c];
        #pragma unroll
        for (int t = 0; t < FTOK; ++t) f[t] += sln[t][dd] * wv;
    }
    #pragma unroll
    for (int t = 0; t < FTOK; ++t) {
        float ff = f[t];
        out[(size_t)(p0 + t) * FDc + c] = ff / (1.0f + __expf(-ff));
    }
}

// ---------------------------------------------------------------------------
extern "C" void kernel_launch(void* const* d_in, const int* in_sizes, int n_in,
                              void* d_out, int out_size)
{
    const float* x      = (const float*)d_in[0];
    const float* g_ln_w = (const float*)d_in[1];
    const float* g_ln_b = (const float*)d_in[2];
    const float* g_w1   = (const float*)d_in[3];
    const float* g_b1   = (const float*)d_in[4];
    const float* g_w2   = (const float*)d_in[5];
    const float* g_b2   = (const float*)d_in[6];
    const float* q_w    = (const float*)d_in[7];
    const float* q_b    = (const float*)d_in[8];
    const float* k_w    = (const float*)d_in[9];
    const float* k_b    = (const float*)d_in[10];
    const float* v_w    = (const float*)d_in[11];
    const float* v_b    = (const float*)d_in[12];
    const float* o_w    = (const float*)d_in[13];
    const float* o_b    = (const float*)d_in[14];
    const float* f_ln_w = (const float*)d_in[15];
    const float* f_ln_b = (const float*)d_in[16];
    const float* f_w    = (const float*)d_in[17];
    const float* f_b    = (const float*)d_in[18];

    // exact CTA count for the (qtile, chunk) decomposition
    int total = 0;
    for (int bx = 0; bx < Lc / TQ3; ++bx) {
        int l0 = Lc - TQ3 * (bx + 1);
        int emax = 6 * ((l0 + TQ3 - 1) / 6) + 6;
        total += (emax + CHUNK - 1) / CHUNK;
    }

    zero_tbs_kernel<<<(Bc*Tt*HIDc + 255) / 256, 256>>>();
    qkv_gate_kernel<<<(Bc * Lc) / QTOK, 128>>>(x, g_ln_w, g_ln_b, g_w1, g_b1,
                                               g_w2, g_b2, q_w, q_b, k_w, k_b,
                                               v_w, v_b);
    scan_sv_kernel<<<Bc * HIDc, Tt>>>();
    attn_kernel<<<dim3(total, NHc, Bc), 128>>>();
    final_kernel<<<(Bc * Tt) / FTOK, 128>>>(o_w, o_b, f_ln_w, f_ln_b, f_w, f_b,
                                            (float*)d_out);
}

// round 7
// speedup vs baseline: 4.4272x; 1.2181x over previous
#include <cuda_runtime.h>
#include <cuda_fp16.h>
#include <math.h>

// Problem constants
#define Bc   2
#define Tt   512
#define Nf   6
#define Dd   32
#define HIDc 128
#define NHc  4
#define HDc  32
#define Lc   3072      // Tt*Nf
#define GHc  32
#define FDc  128
#define EPSc 1e-5f

#define NCHUNK 6
#define CHUNK  512
#define SHIFT  8.0f    // uniform score shift (cancels exactly in O = sum o / sum su)

// Scratch (device globals: no allocation allowed)
__device__ __half d_Qh[Bc*NHc*Lc*HDc];   // fp16 Q (pre-scaled by 1/sqrt(HD)) [bh][l][d]
__device__ __half d_Kh[Bc*NHc*Lc*HDc];   // fp16 K [bh][l][d]
__device__ __half d_Vt[Bc*NHc*HDc*Lc];   // fp16 V transposed [bh][d][l]
__device__ float  d_SV[Bc*Tt*HIDc];      // suffix sums of V beyond block t
__device__ float  d_part[NCHUNK*Bc*Lc*HIDc]; // unnormalized attention partials
__device__ float  d_psum[NCHUNK*Bc*NHc*Lc];  // softmax denominator partials

// D(16x8) += A(16x16,f16) * B(16x8,f16), fp32 accum.
__device__ __forceinline__ void mma_f16(float c[4],
    unsigned a0, unsigned a1, unsigned a2, unsigned a3,
    unsigned b0, unsigned b1)
{
    asm volatile(
        "mma.sync.aligned.m16n8k16.row.col.f32.f16.f16.f32 "
        "{%0,%1,%2,%3}, {%4,%5,%6,%7}, {%8,%9}, {%0,%1,%2,%3};"
        : "+f"(c[0]), "+f"(c[1]), "+f"(c[2]), "+f"(c[3])
        : "r"(a0), "r"(a1), "r"(a2), "r"(a3), "r"(b0), "r"(b1));
}

// ---------------------------------------------------------------------------
// Fused gater + gated QKV. One block (128 threads) per 8 tokens.
#define QTOK 8
__global__ __launch_bounds__(128) void qkv_gate_kernel(const float* __restrict__ x,
    const float* __restrict__ g_ln_w, const float* __restrict__ g_ln_b,
    const float* __restrict__ g_w1,   const float* __restrict__ g_b1,
    const float* __restrict__ g_w2,   const float* __restrict__ g_b2,
    const float* __restrict__ q_w,    const float* __restrict__ q_b,
    const float* __restrict__ k_w,    const float* __restrict__ k_b,
    const float* __restrict__ v_w,    const float* __restrict__ v_b)
{
    const float SC = 0.17677669529663688f;  // 1/sqrt(32)
    int t0 = blockIdx.x * QTOK;
    int tid = threadIdx.x;
    int w = tid >> 5, lane = tid & 31;

    __shared__ float xs[QTOK][32];
    __shared__ float xns[QTOK][32];
    __shared__ float gate[QTOK];

    #pragma unroll
    for (int i = tid; i < QTOK*32; i += 128)
        xs[i >> 5][i & 31] = x[(size_t)t0 * 32 + i];
    __syncthreads();

    // LayerNorm for gater input (warp w: tokens 2w, 2w+1)
    #pragma unroll
    for (int kk = 0; kk < 2; ++kk) {
        int t = w * 2 + kk;
        float xv = xs[t][lane];
        float s = xv, s2 = xv * xv;
        #pragma unroll
        for (int o = 16; o; o >>= 1) {
            s  += __shfl_xor_sync(0xffffffffu, s,  o);
            s2 += __shfl_xor_sync(0xffffffffu, s2, o);
        }
        float mu  = s * (1.0f / 32.0f);
        float var = s2 * (1.0f / 32.0f) - mu * mu;
        xns[t][lane] = (xv - mu) * rsqrtf(var + EPSc) * g_ln_w[lane] + g_ln_b[lane];
    }
    __syncthreads();

    // gater MLP (smem-broadcast matmul)
    #pragma unroll
    for (int kk = 0; kk < 2; ++kk) {
        int t = w * 2 + kk;
        float h = g_b1[lane];
        #pragma unroll
        for (int d = 0; d < 32; ++d)
            h += xns[t][d] * g_w1[d * GHc + lane];
        h = h / (1.0f + __expf(-h));
        float gp = h * g_w2[lane];
        #pragma unroll
        for (int o = 16; o; o >>= 1) gp += __shfl_xor_sync(0xffffffffu, gp, o);
        if (lane == 0) gate[t] = 1.0f / (1.0f + __expf(-(gp + g_b2[0])));
    }
    __syncthreads();

    int c = tid;
    float q[QTOK], k[QTOK], v[QTOK];
    float qb = q_b[c], kb = k_b[c], vb = v_b[c];
    #pragma unroll
    for (int t = 0; t < QTOK; ++t) { q[t] = qb; k[t] = kb; v[t] = vb; }
    #pragma unroll
    for (int dd = 0; dd < 32; ++dd) {
        float wq = q_w[dd * HIDc + c];
        float wk = k_w[dd * HIDc + c];
        float wv = v_w[dd * HIDc + c];
        #pragma unroll
        for (int t = 0; t < QTOK; ++t) {
            float xd = xs[t][dd];
            q[t] += xd * wq; k[t] += xd * wk; v[t] += xd * wv;
        }
    }

    int hh = c >> 5, d2 = c & 31;
    int b = t0 / Lc, lbase = t0 - b * Lc;
    int bh = b * NHc + hh;

    union { __half h[8]; uint4 u; } vp;
    #pragma unroll
    for (int t = 0; t < QTOK; ++t) {
        float g = gate[t];
        size_t idx = ((size_t)bh * Lc + lbase + t) * HDc + d2;
        d_Qh[idx] = __float2half_rn(q[t] * g * SC);
        d_Kh[idx] = __float2half_rn(k[t] * g);
        vp.h[t]   = __float2half_rn(v[t] * g);
    }
    *(uint4*)&d_Vt[((size_t)bh * HDc + d2) * Lc + lbase] = vp.u;
}

// ---------------------------------------------------------------------------
// Suffix sums of V over time blocks, computed directly from d_Vt.
// grid = Bc*HIDc blocks, block = 512 threads (Hillis-Steele).
__global__ void scan_sv_kernel() {
    int col = blockIdx.x;
    int b = col >> 7, c = col & 127;
    int h = c >> 5, d = c & 31;
    int t = threadIdx.x;
    __shared__ float sh[Tt];
    const __half* vp = d_Vt + ((size_t)(b * NHc + h) * HDc + d) * Lc;
    float val = 0.0f;
    #pragma unroll
    for (int k = 0; k < Nf; ++k) val += __half2float(vp[t * Nf + k]);
    sh[t] = val;
    __syncthreads();
    #pragma unroll
    for (int off = 1; off < Tt; off <<= 1) {
        float add = (t + off < Tt) ? sh[t + off] : 0.0f;
        __syncthreads();
        sh[t] += add;
        __syncthreads();
    }
    d_SV[((size_t)b * Tt + t) * HIDc + c] = sh[t] - val;   // exclusive suffix sum
}

// ---------------------------------------------------------------------------
// Tensor-core block-causal attention: fp16 scoring + fp16 PV (fp32 accum),
// split-K over 512-key chunks (additive partials; p=exp(s-8), shift cancels).
// 128 threads, 4 warps x 16 queries = 64 queries/CTA, 32-key tiles.
#define TQ3 64
#define TK3 32
#define KSTH 40  // K smem row stride (halves)
#define VSTR 40  // V^T smem row stride (halves)
#define PSTR 40  // psh row stride (halves)
__global__ __launch_bounds__(128, 7) void attn_kernel()
{
    // map blockIdx.x -> (qtile bx, key chunk)
    int id = blockIdx.x;
    int bx = 0, l0, emax;
    for (;;) {
        l0 = Lc - TQ3 * (bx + 1);
        emax = 6 * ((l0 + TQ3 - 1) / 6) + 6;
        int nch = (emax + CHUNK - 1) / CHUNK;
        if (id < nch) break;
        id -= nch; ++bx;
    }
    int chunk = id;
    int h  = blockIdx.y;
    int b  = blockIdx.z;
    int bh = b * NHc + h;

    const __half* Qb = d_Qh + (size_t)bh * Lc * HDc;
    const __half* Kb = d_Kh + (size_t)bh * Lc * HDc;
    const __half* Vt = d_Vt + (size_t)bh * HDc * Lc;
    float* partp = d_part + (size_t)chunk * (Bc*Lc*HIDc);

    __shared__ __align__(16) __half Ksh[TK3 * KSTH];   // [key][dim]
    __shared__ __align__(16) __half Vsh[HDc * VSTR];   // [dim(32)][key(32)]
    __shared__ __align__(16) __half psh[TQ3 * PSTR];   // [query][key] fp16

    int tid  = threadIdx.x;
    int w    = tid >> 5;
    int lane = tid & 31;
    int g    = lane >> 2;        // groupID
    int tig  = lane & 3;         // thread-in-group
    int qbase = w * 16;

    // Q A-fragments (fp16, k16 steps s=0,1), held in registers
    unsigned qa[2][4];
    const __half* Qp = Qb + (size_t)(l0 + qbase) * 32;
    #pragma unroll
    for (int s = 0; s < 2; ++s) {
        qa[s][0] = *(const unsigned*)(Qp + (size_t)g * 32 + 16*s + 2*tig);
        qa[s][1] = *(const unsigned*)(Qp + (size_t)(g + 8) * 32 + 16*s + 2*tig);
        qa[s][2] = *(const unsigned*)(Qp + (size_t)g * 32 + 16*s + 2*tig + 8);
        qa[s][3] = *(const unsigned*)(Qp + (size_t)(g + 8) * 32 + 16*s + 2*tig + 8);
    }

    int endA = 6 * ((l0 + qbase + g) / 6) + 6;        // causal end, row g
    int endB = 6 * ((l0 + qbase + g + 8) / 6) + 6;    // causal end, row g+8
    int wend = 6 * ((l0 + qbase + 15) / 6) + 6;       // warp's max end

    int kstart = chunk * CHUNK;
    int kend   = min(emax, kstart + CHUNK);           // CTA's chunk range

    float o[2][2][4] = {};       // O^T accum [md][nq][reg]
    float su_lo = 0.f, su_hi = 0.f;

    // tile loader mapping: 128 thr -> 32 rows x 8 halves each
    int trow = tid >> 2;
    int tcol = (tid & 3) * 8;

    uint4 kA = *(const uint4*)(Kb + (size_t)(kstart + trow) * 32 + tcol);
    uint4 vA = *(const uint4*)(Vt + (size_t)trow * Lc + kstart + tcol);

    for (int kb = kstart; kb < kend; kb += TK3) {
        __syncthreads();
        *(uint4*)(Ksh + trow * KSTH + tcol) = kA;
        *(uint4*)(Vsh + trow * VSTR + tcol) = vA;
        if (kb + TK3 < kend) {
            kA = *(const uint4*)(Kb + (size_t)(kb + TK3 + trow) * 32 + tcol);
            vA = *(const uint4*)(Vt + (size_t)trow * Lc + kb + TK3 + tcol);
        }
        __syncthreads();
        if (kb >= wend) continue;   // this warp done; still hits barriers

        // ---- scoring: S(16q x 32k) = Q * K^T via fp16 mma, per 8-key tile j ----
        #pragma unroll
        for (int j = 0; j < 4; ++j) {
            float c[4] = {0.f, 0.f, 0.f, 0.f};
            const __half* kr = Ksh + (8*j + g) * KSTH;
            #pragma unroll
            for (int s = 0; s < 2; ++s) {
                unsigned b0 = *(const unsigned*)(kr + 16*s + 2*tig);
                unsigned b1 = *(const unsigned*)(kr + 16*s + 2*tig + 8);
                mma_f16(c, qa[s][0], qa[s][1], qa[s][2], qa[s][3], b0, b1);
            }
            int ke = kb + 8*j + 2*tig;
            float p0 = (ke     < endA) ? __expf(c[0] - SHIFT) : 0.f;
            float p1 = (ke + 1 < endA) ? __expf(c[1] - SHIFT) : 0.f;
            float p2 = (ke     < endB) ? __expf(c[2] - SHIFT) : 0.f;
            float p3 = (ke + 1 < endB) ? __expf(c[3] - SHIFT) : 0.f;
            __half2 hA = __floats2half2_rn(p0, p1);
            __half2 hB = __floats2half2_rn(p2, p3);
            float2 fA = __half22float2(hA);
            float2 fB = __half22float2(hB);
            su_lo += fA.x + fA.y;
            su_hi += fB.x + fB.y;
            *(__half2*)(psh + (qbase + g) * PSTR + 8*j + 2*tig)     = hA;
            *(__half2*)(psh + (qbase + g + 8) * PSTR + 8*j + 2*tig) = hB;
        }
        __syncwarp();

        // ---- PV: O^T(32d x 16q) += V^T * P^T via fp16 mma ----
        #pragma unroll
        for (int s = 0; s < 2; ++s) {
            unsigned pb00 = *(const unsigned*)(psh + (qbase + g) * PSTR + 16*s + 2*tig);
            unsigned pb01 = *(const unsigned*)(psh + (qbase + g) * PSTR + 16*s + 2*tig + 8);
            unsigned pb10 = *(const unsigned*)(psh + (qbase + 8 + g) * PSTR + 16*s + 2*tig);
            unsigned pb11 = *(const unsigned*)(psh + (qbase + 8 + g) * PSTR + 16*s + 2*tig + 8);
            #pragma unroll
            for (int md = 0; md < 2; ++md) {
                const __half* v0 = Vsh + (16*md + g) * VSTR;
                const __half* v1 = Vsh + (16*md + g + 8) * VSTR;
                unsigned a0 = *(const unsigned*)(v0 + 16*s + 2*tig);
                unsigned a1 = *(const unsigned*)(v1 + 16*s + 2*tig);
                unsigned a2 = *(const unsigned*)(v0 + 16*s + 2*tig + 8);
                unsigned a3 = *(const unsigned*)(v1 + 16*s + 2*tig + 8);
                mma_f16(o[md][0], a0, a1, a2, a3, pb00, pb01);
                mma_f16(o[md][1], a0, a1, a2, a3, pb10, pb11);
            }
        }
        __syncwarp();
    }

    // reduce denominator partials within each quad (over tig)
    su_lo += __shfl_xor_sync(0xffffffffu, su_lo, 1);
    su_lo += __shfl_xor_sync(0xffffffffu, su_lo, 2);
    su_hi += __shfl_xor_sync(0xffffffffu, su_hi, 1);
    su_hi += __shfl_xor_sync(0xffffffffu, su_hi, 2);
    if (tig == 0) {
        size_t sb = (size_t)chunk * (Bc*NHc*Lc) + (size_t)bh * Lc + l0 + qbase;
        d_psum[sb + g]     = su_lo;
        d_psum[sb + g + 8] = su_hi;
    }

    #pragma unroll
    for (int md = 0; md < 2; ++md) {
        #pragma unroll
        for (int nq = 0; nq < 2; ++nq) {
            int qloc = qbase + 8*nq + 2*tig;
            size_t base = ((size_t)b * Lc + l0 + qloc) * HIDc + h * HDc + 16*md + g;
            partp[base]            = o[md][nq][0];
            partp[base + HIDc]     = o[md][nq][1];
            partp[base + 8]        = o[md][nq][2];
            partp[base + HIDc + 8] = o[md][nq][3];
        }
    }
}

// ---------------------------------------------------------------------------
// Combine split-K partials + pool(6) + exact 1e-9 masked tail -> o_w -> LN
// -> f_w -> SiLU.  8 (b,t) rows per block.
#define FTOK 8
__global__ __launch_bounds__(128) void final_kernel(
    const float* __restrict__ o_w,    const float* __restrict__ o_b,
    const float* __restrict__ f_ln_w, const float* __restrict__ f_ln_b,
    const float* __restrict__ f_w,    const float* __restrict__ f_b,
    float* __restrict__ out)
{
    int p0 = blockIdx.x * FTOK;
    int c = threadIdx.x;
    int w = c >> 5, lane = c & 31;
    int h = c >> 5;

    __shared__ float sp[FTOK][128];
    __shared__ float sln[FTOK][128];
    __shared__ float redA[FTOK][4], redB[FTOK][4];

    #pragma unroll
    for (int t = 0; t < FTOK; ++t) {
        int bt = p0 + t;
        int b = bt / Tt, tt = bt - b * Tt;
        int end = tt * Nf + Nf;
        int nc = (end + CHUNK - 1) / CHUNK;  // live chunks
        float p = 0.0f;
        #pragma unroll
        for (int k = 0; k < Nf; ++k) {
            int l = tt * Nf + k;
            float su = 0.f, oo = 0.f;
            for (int cc = 0; cc < nc; ++cc) {
                su += d_psum[(size_t)cc * (Bc*NHc*Lc) + ((size_t)b*NHc + h)*Lc + l];
                oo += d_part[(size_t)cc * (Bc*Lc*HIDc) + ((size_t)b*Lc + l)*HIDc + c];
            }
            p += oo / su;
        }
        sp[t][c] = p * (1.0f / Nf) + 1e-9f * d_SV[((size_t)b * Tt + tt) * HIDc + c];
    }
    __syncthreads();

    float acc[FTOK];
    float ob = o_b[c];
    #pragma unroll
    for (int t = 0; t < FTOK; ++t) acc[t] = ob;
    #pragma unroll 4
    for (int dd = 0; dd < 128; ++dd) {
        float wv = o_w[dd * HIDc + c];
        #pragma unroll
        for (int t = 0; t < FTOK; ++t) acc[t] += sp[t][dd] * wv;
    }

    #pragma unroll
    for (int t = 0; t < FTOK; ++t) {
        float s = acc[t], s2 = acc[t] * acc[t];
        #pragma unroll
        for (int o = 16; o; o >>= 1) {
            s  += __shfl_xor_sync(0xffffffffu, s,  o);
            s2 += __shfl_xor_sync(0xffffffffu, s2, o);
        }
        if (lane == 0) { redA[t][w] = s; redB[t][w] = s2; }
    }
    __syncthreads();
    #pragma unroll
    for (int t = 0; t < FTOK; ++t) {
        float S  = redA[t][0] + redA[t][1] + redA[t][2] + redA[t][3];
        float S2 = redB[t][0] + redB[t][1] + redB[t][2] + redB[t][3];
        float mu  = S * (1.0f / 128.0f);
        float var = S2 * (1.0f / 128.0f) - mu * mu;
        sln[t][c] = (acc[t] - mu) * rsqrtf(var + EPSc) * f_ln_w[c] + f_ln_b[c];
    }
    __syncthreads();

    float f[FTOK];
    float fb = f_b[c];
    #pragma unroll
    for (int t = 0; t < FTOK; ++t) f[t] = fb;
    #pragma unroll 4
    for (int dd = 0; dd < 128; ++dd) {
        float wv = f_w[dd * HIDc + c];
        #pragma unroll
        for (int t = 0; t < FTOK; ++t) f[t] += sln[t][dd] * wv;
    }
    #pragma unroll
    for (int t = 0; t < FTOK; ++t) {
        float ff = f[t];
        out[(size_t)(p0 + t) * FDc + c] = ff / (1.0f + __expf(-ff));
    }
}

// ---------------------------------------------------------------------------
extern "C" void kernel_launch(void* const* d_in, const int* in_sizes, int n_in,
                              void* d_out, int out_size)
{
    const float* x      = (const float*)d_in[0];
    const float* g_ln_w = (const float*)d_in[1];
    const float* g_ln_b = (const float*)d_in[2];
    const float* g_w1   = (const float*)d_in[3];
    const float* g_b1   = (const float*)d_in[4];
    const float* g_w2   = (const float*)d_in[5];
    const float* g_b2   = (const float*)d_in[6];
    const float* q_w    = (const float*)d_in[7];
    const float* q_b    = (const float*)d_in[8];
    const float* k_w    = (const float*)d_in[9];
    const float* k_b    = (const float*)d_in[10];
    const float* v_w    = (const float*)d_in[11];
    const float* v_b    = (const float*)d_in[12];
    const float* o_w    = (const float*)d_in[13];
    const float* o_b    = (const float*)d_in[14];
    const float* f_ln_w = (const float*)d_in[15];
    const float* f_ln_b = (const float*)d_in[16];
    const float* f_w    = (const float*)d_in[17];
    const float* f_b    = (const float*)d_in[18];

    // exact CTA count for the (qtile, chunk) decomposition
    int total = 0;
    for (int bx = 0; bx < Lc / TQ3; ++bx) {
        int l0 = Lc - TQ3 * (bx + 1);
        int emax = 6 * ((l0 + TQ3 - 1) / 6) + 6;
        total += (emax + CHUNK - 1) / CHUNK;
    }

    qkv_gate_kernel<<<(Bc * Lc) / QTOK, 128>>>(x, g_ln_w, g_ln_b, g_w1, g_b1,
                                               g_w2, g_b2, q_w, q_b, k_w, k_b,
                                               v_w, v_b);
    scan_sv_kernel<<<Bc * HIDc, Tt>>>();
    attn_kernel<<<dim3(total, NHc, Bc), 128>>>();
    final_kernel<<<(Bc * Tt) / FTOK, 128>>>(o_w, o_b, f_ln_w, f_ln_b, f_w, f_b,
                                            (float*)d_out);
}

// round 8
// speedup vs baseline: 6.6854x; 1.5101x over previous
#include <cuda_runtime.h>
#include <cuda_fp16.h>
#include <math.h>

// Problem constants
#define Bc   2
#define Tt   512
#define Nf   6
#define Dd   32
#define HIDc 128
#define NHc  4
#define HDc  32
#define Lc   3072      // Tt*Nf
#define GHc  32
#define FDc  128
#define EPSc 1e-5f

#define NCHUNK 6
#define CHUNK  512
#define SHIFT  8.0f    // uniform score shift (cancels exactly in O = sum o / sum su)

// Scratch (device globals: no allocation allowed)
__device__ __half d_Qh[Bc*NHc*Lc*HDc];   // fp16 Q (pre-scaled by 1/sqrt(HD)) [bh][l][d]
__device__ __half d_Kh[Bc*NHc*Lc*HDc];   // fp16 K [bh][l][d]
__device__ __half d_Vt[Bc*NHc*HDc*Lc];   // fp16 V transposed [bh][d][l]
__device__ float  d_SV[Bc*Tt*HIDc];      // suffix sums of V beyond block t
__device__ float  d_part[NCHUNK*Bc*Lc*HIDc]; // unnormalized attention partials
__device__ float  d_psum[NCHUNK*Bc*NHc*Lc];  // softmax denominator partials
__device__ float  d_SP[Bc*Tt*HIDc];      // pooled attention rows (pre o_w)

// D(16x8) += A(16x16,f16) * B(16x8,f16), fp32 accum.
__device__ __forceinline__ void mma_f16(float c[4],
    unsigned a0, unsigned a1, unsigned a2, unsigned a3,
    unsigned b0, unsigned b1)
{
    asm volatile(
        "mma.sync.aligned.m16n8k16.row.col.f32.f16.f16.f32 "
        "{%0,%1,%2,%3}, {%4,%5,%6,%7}, {%8,%9}, {%0,%1,%2,%3};"
        : "+f"(c[0]), "+f"(c[1]), "+f"(c[2]), "+f"(c[3])
        : "r"(a0), "r"(a1), "r"(a2), "r"(a3), "r"(b0), "r"(b1));
}

// ---------------------------------------------------------------------------
// Fused gater + gated QKV. One block (128 threads) per 8 tokens.
#define QTOK 8
__global__ __launch_bounds__(128) void qkv_gate_kernel(const float* __restrict__ x,
    const float* __restrict__ g_ln_w, const float* __restrict__ g_ln_b,
    const float* __restrict__ g_w1,   const float* __restrict__ g_b1,
    const float* __restrict__ g_w2,   const float* __restrict__ g_b2,
    const float* __restrict__ q_w,    const float* __restrict__ q_b,
    const float* __restrict__ k_w,    const float* __restrict__ k_b,
    const float* __restrict__ v_w,    const float* __restrict__ v_b)
{
    const float SC = 0.17677669529663688f;  // 1/sqrt(32)
    int t0 = blockIdx.x * QTOK;
    int tid = threadIdx.x;
    int w = tid >> 5, lane = tid & 31;

    __shared__ float xs[QTOK][32];
    __shared__ float xns[QTOK][32];
    __shared__ float gate[QTOK];

    #pragma unroll
    for (int i = tid; i < QTOK*32; i += 128)
        xs[i >> 5][i & 31] = x[(size_t)t0 * 32 + i];
    __syncthreads();

    // LayerNorm for gater input (warp w: tokens 2w, 2w+1)
    #pragma unroll
    for (int kk = 0; kk < 2; ++kk) {
        int t = w * 2 + kk;
        float xv = xs[t][lane];
        float s = xv, s2 = xv * xv;
        #pragma unroll
        for (int o = 16; o; o >>= 1) {
            s  += __shfl_xor_sync(0xffffffffu, s,  o);
            s2 += __shfl_xor_sync(0xffffffffu, s2, o);
        }
        float mu  = s * (1.0f / 32.0f);
        float var = s2 * (1.0f / 32.0f) - mu * mu;
        xns[t][lane] = (xv - mu) * rsqrtf(var + EPSc) * g_ln_w[lane] + g_ln_b[lane];
    }
    __syncthreads();

    // gater MLP (smem-broadcast matmul)
    #pragma unroll
    for (int kk = 0; kk < 2; ++kk) {
        int t = w * 2 + kk;
        float h = g_b1[lane];
        #pragma unroll
        for (int d = 0; d < 32; ++d)
            h += xns[t][d] * g_w1[d * GHc + lane];
        h = h / (1.0f + __expf(-h));
        float gp = h * g_w2[lane];
        #pragma unroll
        for (int o = 16; o; o >>= 1) gp += __shfl_xor_sync(0xffffffffu, gp, o);
        if (lane == 0) gate[t] = 1.0f / (1.0f + __expf(-(gp + g_b2[0])));
    }
    __syncthreads();

    int c = tid;
    float q[QTOK], k[QTOK], v[QTOK];
    float qb = q_b[c], kb = k_b[c], vb = v_b[c];
    #pragma unroll
    for (int t = 0; t < QTOK; ++t) { q[t] = qb; k[t] = kb; v[t] = vb; }
    #pragma unroll
    for (int dd = 0; dd < 32; ++dd) {
        float wq = q_w[dd * HIDc + c];
        float wk = k_w[dd * HIDc + c];
        float wv = v_w[dd * HIDc + c];
        #pragma unroll
        for (int t = 0; t < QTOK; ++t) {
            float xd = xs[t][dd];
            q[t] += xd * wq; k[t] += xd * wk; v[t] += xd * wv;
        }
    }

    int hh = c >> 5, d2 = c & 31;
    int b = t0 / Lc, lbase = t0 - b * Lc;
    int bh = b * NHc + hh;

    union { __half h[8]; uint4 u; } vp;
    #pragma unroll
    for (int t = 0; t < QTOK; ++t) {
        float g = gate[t];
        size_t idx = ((size_t)bh * Lc + lbase + t) * HDc + d2;
        d_Qh[idx] = __float2half_rn(q[t] * g * SC);
        d_Kh[idx] = __float2half_rn(k[t] * g);
        vp.h[t]   = __float2half_rn(v[t] * g);
    }
    *(uint4*)&d_Vt[((size_t)bh * HDc + d2) * Lc + lbase] = vp.u;
}

// ---------------------------------------------------------------------------
// Suffix sums of V over time blocks, computed directly from d_Vt.
// grid = Bc*HIDc blocks, block = 512 threads (Hillis-Steele).
__global__ void scan_sv_kernel() {
    int col = blockIdx.x;
    int b = col >> 7, c = col & 127;
    int h = c >> 5, d = c & 31;
    int t = threadIdx.x;
    __shared__ float sh[Tt];
    const __half* vp = d_Vt + ((size_t)(b * NHc + h) * HDc + d) * Lc;
    float val = 0.0f;
    #pragma unroll
    for (int k = 0; k < Nf; ++k) val += __half2float(vp[t * Nf + k]);
    sh[t] = val;
    __syncthreads();
    #pragma unroll
    for (int off = 1; off < Tt; off <<= 1) {
        float add = (t + off < Tt) ? sh[t + off] : 0.0f;
        __syncthreads();
        sh[t] += add;
        __syncthreads();
    }
    d_SV[((size_t)b * Tt + t) * HIDc + c] = sh[t] - val;   // exclusive suffix sum
}

// ---------------------------------------------------------------------------
// Tensor-core block-causal attention: fp16 scoring + fp16 PV (fp32 accum),
// split-K over 512-key chunks (additive partials; p=exp(s-8), shift cancels).
// 128 threads, 4 warps x 16 queries = 64 queries/CTA, 32-key tiles.
#define TQ3 64
#define TK3 32
#define KSTH 40  // K smem row stride (halves)
#define VSTR 40  // V^T smem row stride (halves)
#define PSTR 40  // psh row stride (halves)
__global__ __launch_bounds__(128, 7) void attn_kernel()
{
    // map blockIdx.x -> (qtile bx, key chunk)
    int id = blockIdx.x;
    int bx = 0, l0, emax;
    for (;;) {
        l0 = Lc - TQ3 * (bx + 1);
        emax = 6 * ((l0 + TQ3 - 1) / 6) + 6;
        int nch = (emax + CHUNK - 1) / CHUNK;
        if (id < nch) break;
        id -= nch; ++bx;
    }
    int chunk = id;
    int h  = blockIdx.y;
    int b  = blockIdx.z;
    int bh = b * NHc + h;

    const __half* Qb = d_Qh + (size_t)bh * Lc * HDc;
    const __half* Kb = d_Kh + (size_t)bh * Lc * HDc;
    const __half* Vt = d_Vt + (size_t)bh * HDc * Lc;
    float* partp = d_part + (size_t)chunk * (Bc*Lc*HIDc);

    __shared__ __align__(16) __half Ksh[TK3 * KSTH];   // [key][dim]
    __shared__ __align__(16) __half Vsh[HDc * VSTR];   // [dim(32)][key(32)]
    __shared__ __align__(16) __half psh[TQ3 * PSTR];   // [query][key] fp16

    int tid  = threadIdx.x;
    int w    = tid >> 5;
    int lane = tid & 31;
    int g    = lane >> 2;        // groupID
    int tig  = lane & 3;         // thread-in-group
    int qbase = w * 16;

    // Q A-fragments (fp16, k16 steps s=0,1), held in registers
    unsigned qa[2][4];
    const __half* Qp = Qb + (size_t)(l0 + qbase) * 32;
    #pragma unroll
    for (int s = 0; s < 2; ++s) {
        qa[s][0] = *(const unsigned*)(Qp + (size_t)g * 32 + 16*s + 2*tig);
        qa[s][1] = *(const unsigned*)(Qp + (size_t)(g + 8) * 32 + 16*s + 2*tig);
        qa[s][2] = *(const unsigned*)(Qp + (size_t)g * 32 + 16*s + 2*tig + 8);
        qa[s][3] = *(const unsigned*)(Qp + (size_t)(g + 8) * 32 + 16*s + 2*tig + 8);
    }

    int endA = 6 * ((l0 + qbase + g) / 6) + 6;        // causal end, row g
    int endB = 6 * ((l0 + qbase + g + 8) / 6) + 6;    // causal end, row g+8
    int wend = 6 * ((l0 + qbase + 15) / 6) + 6;       // warp's max end

    int kstart = chunk * CHUNK;
    int kend   = min(emax, kstart + CHUNK);           // CTA's chunk range

    float o[2][2][4] = {};       // O^T accum [md][nq][reg]
    float su_lo = 0.f, su_hi = 0.f;

    // tile loader mapping: 128 thr -> 32 rows x 8 halves each
    int trow = tid >> 2;
    int tcol = (tid & 3) * 8;

    uint4 kA = *(const uint4*)(Kb + (size_t)(kstart + trow) * 32 + tcol);
    uint4 vA = *(const uint4*)(Vt + (size_t)trow * Lc + kstart + tcol);

    for (int kb = kstart; kb < kend; kb += TK3) {
        __syncthreads();
        *(uint4*)(Ksh + trow * KSTH + tcol) = kA;
        *(uint4*)(Vsh + trow * VSTR + tcol) = vA;
        if (kb + TK3 < kend) {
            kA = *(const uint4*)(Kb + (size_t)(kb + TK3 + trow) * 32 + tcol);
            vA = *(const uint4*)(Vt + (size_t)trow * Lc + kb + TK3 + tcol);
        }
        __syncthreads();
        if (kb >= wend) continue;   // this warp done; still hits barriers

        // ---- scoring: S(16q x 32k) = Q * K^T via fp16 mma, per 8-key tile j ----
        #pragma unroll
        for (int j = 0; j < 4; ++j) {
            float c[4] = {0.f, 0.f, 0.f, 0.f};
            const __half* kr = Ksh + (8*j + g) * KSTH;
            #pragma unroll
            for (int s = 0; s < 2; ++s) {
                unsigned b0 = *(const unsigned*)(kr + 16*s + 2*tig);
                unsigned b1 = *(const unsigned*)(kr + 16*s + 2*tig + 8);
                mma_f16(c, qa[s][0], qa[s][1], qa[s][2], qa[s][3], b0, b1);
            }
            int ke = kb + 8*j + 2*tig;
            float p0 = (ke     < endA) ? __expf(c[0] - SHIFT) : 0.f;
            float p1 = (ke + 1 < endA) ? __expf(c[1] - SHIFT) : 0.f;
            float p2 = (ke     < endB) ? __expf(c[2] - SHIFT) : 0.f;
            float p3 = (ke + 1 < endB) ? __expf(c[3] - SHIFT) : 0.f;
            __half2 hA = __floats2half2_rn(p0, p1);
            __half2 hB = __floats2half2_rn(p2, p3);
            float2 fA = __half22float2(hA);
            float2 fB = __half22float2(hB);
            su_lo += fA.x + fA.y;
            su_hi += fB.x + fB.y;
            *(__half2*)(psh + (qbase + g) * PSTR + 8*j + 2*tig)     = hA;
            *(__half2*)(psh + (qbase + g + 8) * PSTR + 8*j + 2*tig) = hB;
        }
        __syncwarp();

        // ---- PV: O^T(32d x 16q) += V^T * P^T via fp16 mma ----
        #pragma unroll
        for (int s = 0; s < 2; ++s) {
            unsigned pb00 = *(const unsigned*)(psh + (qbase + g) * PSTR + 16*s + 2*tig);
            unsigned pb01 = *(const unsigned*)(psh + (qbase + g) * PSTR + 16*s + 2*tig + 8);
            unsigned pb10 = *(const unsigned*)(psh + (qbase + 8 + g) * PSTR + 16*s + 2*tig);
            unsigned pb11 = *(const unsigned*)(psh + (qbase + 8 + g) * PSTR + 16*s + 2*tig + 8);
            #pragma unroll
            for (int md = 0; md < 2; ++md) {
                const __half* v0 = Vsh + (16*md + g) * VSTR;
                const __half* v1 = Vsh + (16*md + g + 8) * VSTR;
                unsigned a0 = *(const unsigned*)(v0 + 16*s + 2*tig);
                unsigned a1 = *(const unsigned*)(v1 + 16*s + 2*tig);
                unsigned a2 = *(const unsigned*)(v0 + 16*s + 2*tig + 8);
                unsigned a3 = *(const unsigned*)(v1 + 16*s + 2*tig + 8);
                mma_f16(o[md][0], a0, a1, a2, a3, pb00, pb01);
                mma_f16(o[md][1], a0, a1, a2, a3, pb10, pb11);
            }
        }
        __syncwarp();
    }

    // reduce denominator partials within each quad (over tig)
    su_lo += __shfl_xor_sync(0xffffffffu, su_lo, 1);
    su_lo += __shfl_xor_sync(0xffffffffu, su_lo, 2);
    su_hi += __shfl_xor_sync(0xffffffffu, su_hi, 1);
    su_hi += __shfl_xor_sync(0xffffffffu, su_hi, 2);
    if (tig == 0) {
        size_t sb = (size_t)chunk * (Bc*NHc*Lc) + (size_t)bh * Lc + l0 + qbase;
        d_psum[sb + g]     = su_lo;
        d_psum[sb + g + 8] = su_hi;
    }

    #pragma unroll
    for (int md = 0; md < 2; ++md) {
        #pragma unroll
        for (int nq = 0; nq < 2; ++nq) {
            int qloc = qbase + 8*nq + 2*tig;
            size_t base = ((size_t)b * Lc + l0 + qloc) * HIDc + h * HDc + 16*md + g;
            partp[base]            = o[md][nq][0];
            partp[base + HIDc]     = o[md][nq][1];
            partp[base + 8]        = o[md][nq][2];
            partp[base + HIDc + 8] = o[md][nq][3];
        }
    }
}

// ---------------------------------------------------------------------------
// Combine split-K partials + pool(6) + exact 1e-9 masked tail -> d_SP.
// grid = Bc*Tt blocks x 128 threads; fully unrolled independent loads.
__global__ __launch_bounds__(128) void combine_kernel()
{
    int bt = blockIdx.x;
    int b = bt / Tt, tt = bt - b * Tt;
    int c = threadIdx.x;
    int h = c >> 5;

    int end = tt * Nf + Nf;
    int nc = (end + CHUNK - 1) / CHUNK;   // live chunks for this time block

    float p = 0.0f;
    #pragma unroll
    for (int k = 0; k < Nf; ++k) {
        int l = tt * Nf + k;
        float su = 0.f, oo = 0.f;
        #pragma unroll
        for (int cc = 0; cc < NCHUNK; ++cc) {
            if (cc < nc) {
                su += d_psum[(size_t)cc * (Bc*NHc*Lc) + ((size_t)b*NHc + h)*Lc + l];
                oo += d_part[(size_t)cc * (Bc*Lc*HIDc) + ((size_t)b*Lc + l)*HIDc + c];
            }
        }
        p += oo / su;
    }
    d_SP[(size_t)bt * HIDc + c] =
        p * (1.0f / Nf) + 1e-9f * d_SV[(size_t)bt * HIDc + c];
}

// ---------------------------------------------------------------------------
// o_w -> LN -> f_w -> SiLU on pooled rows.  4 rows per block, 256 blocks.
#define FTOK 4
__global__ __launch_bounds__(128) void final_kernel(
    const float* __restrict__ o_w,    const float* __restrict__ o_b,
    const float* __restrict__ f_ln_w, const float* __restrict__ f_ln_b,
    const float* __restrict__ f_w,    const float* __restrict__ f_b,
    float* __restrict__ out)
{
    int p0 = blockIdx.x * FTOK;
    int c = threadIdx.x;
    int w = c >> 5, lane = c & 31;

    __shared__ float sp[FTOK][128];
    __shared__ float sln[FTOK][128];
    __shared__ float redA[FTOK][4], redB[FTOK][4];

    #pragma unroll
    for (int t = 0; t < FTOK; ++t)
        sp[t][c] = d_SP[(size_t)(p0 + t) * HIDc + c];
    __syncthreads();

    float acc[FTOK];
    float ob = o_b[c];
    #pragma unroll
    for (int t = 0; t < FTOK; ++t) acc[t] = ob;
    #pragma unroll 8
    for (int dd = 0; dd < 128; ++dd) {
        float wv = o_w[dd * HIDc + c];
        #pragma unroll
        for (int t = 0; t < FTOK; ++t) acc[t] += sp[t][dd] * wv;
    }

    #pragma unroll
    for (int t = 0; t < FTOK; ++t) {
        float s = acc[t], s2 = acc[t] * acc[t];
        #pragma unroll
        for (int o = 16; o; o >>= 1) {
            s  += __shfl_xor_sync(0xffffffffu, s,  o);
            s2 += __shfl_xor_sync(0xffffffffu, s2, o);
        }
        if (lane == 0) { redA[t][w] = s; redB[t][w] = s2; }
    }
    __syncthreads();
    #pragma unroll
    for (int t = 0; t < FTOK; ++t) {
        float S  = redA[t][0] + redA[t][1] + redA[t][2] + redA[t][3];
        float S2 = redB[t][0] + redB[t][1] + redB[t][2] + redB[t][3];
        float mu  = S * (1.0f / 128.0f);
        float var = S2 * (1.0f / 128.0f) - mu * mu;
        sln[t][c] = (acc[t] - mu) * rsqrtf(var + EPSc) * f_ln_w[c] + f_ln_b[c];
    }
    __syncthreads();

    float f[FTOK];
    float fb = f_b[c];
    #pragma unroll
    for (int t = 0; t < FTOK; ++t) f[t] = fb;
    #pragma unroll 8
    for (int dd = 0; dd < 128; ++dd) {
        float wv = f_w[dd * HIDc + c];
        #pragma unroll
        for (int t = 0; t < FTOK; ++t) f[t] += sln[t][dd] * wv;
    }
    #pragma unroll
    for (int t = 0; t < FTOK; ++t) {
        float ff = f[t];
        out[(size_t)(p0 + t) * FDc + c] = ff / (1.0f + __expf(-ff));
    }
}

// ---------------------------------------------------------------------------
extern "C" void kernel_launch(void* const* d_in, const int* in_sizes, int n_in,
                              void* d_out, int out_size)
{
    const float* x      = (const float*)d_in[0];
    const float* g_ln_w = (const float*)d_in[1];
    const float* g_ln_b = (const float*)d_in[2];
    const float* g_w1   = (const float*)d_in[3];
    const float* g_b1   = (const float*)d_in[4];
    const float* g_w2   = (const float*)d_in[5];
    const float* g_b2   = (const float*)d_in[6];
    const float* q_w    = (const float*)d_in[7];
    const float* q_b    = (const float*)d_in[8];
    const float* k_w    = (const float*)d_in[9];
    const float* k_b    = (const float*)d_in[10];
    const float* v_w    = (const float*)d_in[11];
    const float* v_b    = (const float*)d_in[12];
    const float* o_w    = (const float*)d_in[13];
    const float* o_b    = (const float*)d_in[14];
    const float* f_ln_w = (const float*)d_in[15];
    const float* f_ln_b = (const float*)d_in[16];
    const float* f_w    = (const float*)d_in[17];
    const float* f_b    = (const float*)d_in[18];

    // exact CTA count for the (qtile, chunk) decomposition
    int total = 0;
    for (int bx = 0; bx < Lc / TQ3; ++bx) {
        int l0 = Lc - TQ3 * (bx + 1);
        int emax = 6 * ((l0 + TQ3 - 1) / 6) + 6;
        total += (emax + CHUNK - 1) / CHUNK;
    }

    qkv_gate_kernel<<<(Bc * Lc) / QTOK, 128>>>(x, g_ln_w, g_ln_b, g_w1, g_b1,
                                               g_w2, g_b2, q_w, q_b, k_w, k_b,
                                               v_w, v_b);
    scan_sv_kernel<<<Bc * HIDc, Tt>>>();
    attn_kernel<<<dim3(total, NHc, Bc), 128>>>();
    combine_kernel<<<Bc * Tt, 128>>>();
    final_kernel<<<(Bc * Tt) / FTOK, 128>>>(o_w, o_b, f_ln_w, f_ln_b, f_w, f_b,
                                            (float*)d_out);
}